// round 1
// baseline (speedup 1.0000x reference)
#include <cuda_runtime.h>
#include <math.h>

#define T_TOKENS 8192
#define H_DIM    512
#define I_DIM    1024
#define E_NUM    8
#define NP       (T_TOKENS * 2)   // token-expert pairs (top-2)

// ---------------- scratch (device globals; no runtime allocation) ------------
__device__ int   g_count[E_NUM];
__device__ int   g_cursor[E_NUM];
__device__ int   g_off[E_NUM + 1];
__device__ int   g_tok_e[T_TOKENS * 2];
__device__ float g_tok_w[T_TOKENS * 2];
__device__ int   g_list_tok[NP];
__device__ float g_list_w[NP];
__device__ float g_h[(size_t)NP * I_DIM];   // 64 MB intermediate relu(xW1+b1)

// ---------------- small helpers ----------------------------------------------
__global__ void zero_small_kernel() {
    int i = threadIdx.x;
    if (i < E_NUM) { g_count[i] = 0; g_cursor[i] = 0; }
}

__global__ void zero_out_kernel(float4* __restrict__ out4, int n4) {
    int i = blockIdx.x * blockDim.x + threadIdx.x;
    if (i < n4) out4[i] = make_float4(0.f, 0.f, 0.f, 0.f);
}

// ---------------- router: logits, softmax, top-2, counts ---------------------
__global__ void router_kernel(const float* __restrict__ x,
                              const float* __restrict__ gw,
                              float* __restrict__ logits_out) {
    __shared__ int s_cnt[E_NUM];
    int tid = threadIdx.x;
    if (tid < E_NUM) s_cnt[tid] = 0;
    __syncthreads();

    int warp = tid >> 5, lane = tid & 31;
    int t = blockIdx.x * 8 + warp;
    if (t < T_TOKENS) {
        float xr[16];
        #pragma unroll
        for (int j = 0; j < 16; j++) xr[j] = x[(size_t)t * H_DIM + lane + 32 * j];
        float lg[E_NUM];
        #pragma unroll
        for (int e = 0; e < E_NUM; e++) {
            float s = 0.f;
            const float* g = gw + (size_t)e * H_DIM + lane;
            #pragma unroll
            for (int j = 0; j < 16; j++) s = fmaf(xr[j], g[32 * j], s);
            #pragma unroll
            for (int o = 16; o; o >>= 1) s += __shfl_xor_sync(0xffffffffu, s, o);
            lg[e] = s;
        }
        if (lane == 0) {
            float m = lg[0];
            #pragma unroll
            for (int e = 1; e < E_NUM; e++) m = fmaxf(m, lg[e]);
            float p[E_NUM], sum = 0.f;
            #pragma unroll
            for (int e = 0; e < E_NUM; e++) { p[e] = expf(lg[e] - m); sum += p[e]; }
            float inv = 1.f / sum;
            #pragma unroll
            for (int e = 0; e < E_NUM; e++) {
                p[e] *= inv;
                logits_out[(size_t)t * E_NUM + e] = lg[e];
            }
            // top-2 (first occurrence wins ties, matching lax.top_k)
            int i0 = 0;
            #pragma unroll
            for (int e = 1; e < E_NUM; e++) if (p[e] > p[i0]) i0 = e;
            int i1 = (i0 == 0) ? 1 : 0;
            #pragma unroll
            for (int e = 0; e < E_NUM; e++) if (e != i1 && e != i0 && p[e] > p[i1]) i1 = e;
            float w0 = p[i0], w1 = p[i1];
            float s2 = w0 + w1 + 1e-20f;
            w0 = (w0 / s2) * 0.5f;
            w1 = (w1 / s2) * 0.5f;
            g_tok_e[t * 2 + 0] = i0;  g_tok_w[t * 2 + 0] = w0;
            g_tok_e[t * 2 + 1] = i1;  g_tok_w[t * 2 + 1] = w1;
            atomicAdd(&s_cnt[i0], 1);
            atomicAdd(&s_cnt[i1], 1);
        }
    }
    __syncthreads();
    if (tid < E_NUM && s_cnt[tid]) atomicAdd(&g_count[tid], s_cnt[tid]);
}

__global__ void scan_kernel() {
    int o = 0;
    for (int e = 0; e < E_NUM; e++) { g_off[e] = o; o += g_count[e]; }
    g_off[E_NUM] = o;
}

__global__ void scatter_kernel() {
    int t = blockIdx.x * 256 + threadIdx.x;
    if (t >= T_TOKENS) return;
    #pragma unroll
    for (int k = 0; k < 2; k++) {
        int e = g_tok_e[t * 2 + k];
        int pos = atomicAdd(&g_cursor[e], 1);
        int idx = g_off[e] + pos;
        g_list_tok[idx] = t;
        g_list_w[idx]   = g_tok_w[t * 2 + k];
    }
}

// ---------------- GEMM1: h = relu(x_gather @ W1[e] + b1[e]) ------------------
// tiles: 64(M) x 64(N) x 16(K), 256 threads, 4x4 register micro-tile
__global__ void gemm1_kernel(const float* __restrict__ x,
                             const float* __restrict__ w1,
                             const float* __restrict__ b1) {
    int e = blockIdx.z;
    int cnt = g_count[e];
    int m_base = blockIdx.y * 64;
    if (m_base >= cnt) return;
    int off = g_off[e];
    int n_base = blockIdx.x * 64;

    __shared__ float As[16][64];
    __shared__ float Bs[16][64];

    int tid = threadIdx.x;
    int am = tid >> 2, ak4 = (tid & 3) * 4;       // A: 64 rows x 4 float4-cols
    int arow = m_base + am;
    bool avalid = arow < cnt;
    int tok = avalid ? g_list_tok[off + arow] : 0;
    const float* aptr = x + (size_t)tok * H_DIM + ak4;

    int bk = tid >> 4, bn4 = (tid & 15) * 4;      // B: 16 k-rows x 16 float4-cols
    const float* bptr = w1 + (size_t)e * H_DIM * I_DIM + (size_t)bk * I_DIM + n_base + bn4;

    int tx = tid & 15, ty = tid >> 4;
    float acc[4][4] = {};

    for (int k0 = 0; k0 < H_DIM; k0 += 16) {
        float4 av = avalid ? *(const float4*)(aptr + k0) : make_float4(0, 0, 0, 0);
        As[ak4 + 0][am] = av.x; As[ak4 + 1][am] = av.y;
        As[ak4 + 2][am] = av.z; As[ak4 + 3][am] = av.w;
        float4 bv = *(const float4*)(bptr + (size_t)k0 * I_DIM);
        *(float4*)&Bs[bk][bn4] = bv;
        __syncthreads();
        #pragma unroll
        for (int k = 0; k < 16; k++) {
            float4 a = *(const float4*)&As[k][ty << 2];
            float4 b = *(const float4*)&Bs[k][tx << 2];
            float ar[4] = {a.x, a.y, a.z, a.w};
            float br[4] = {b.x, b.y, b.z, b.w};
            #pragma unroll
            for (int i = 0; i < 4; i++)
                #pragma unroll
                for (int j = 0; j < 4; j++)
                    acc[i][j] = fmaf(ar[i], br[j], acc[i][j]);
        }
        __syncthreads();
    }

    #pragma unroll
    for (int i = 0; i < 4; i++) {
        int r = m_base + (ty << 2) + i;
        if (r >= cnt) continue;
        size_t p = (size_t)(off + r);
        #pragma unroll
        for (int j = 0; j < 4; j++) {
            int n = n_base + (tx << 2) + j;
            float v = acc[i][j] + b1[e * I_DIM + n];
            g_h[p * I_DIM + n] = fmaxf(v, 0.f);
        }
    }
}

// ---------------- GEMM2: out[tok] += w * (h @ W2[e] + b2[e]) -----------------
__global__ void gemm2_kernel(const float* __restrict__ w2,
                             const float* __restrict__ b2,
                             float* __restrict__ out) {
    int e = blockIdx.z;
    int cnt = g_count[e];
    int m_base = blockIdx.y * 64;
    if (m_base >= cnt) return;
    int off = g_off[e];
    int n_base = blockIdx.x * 64;

    __shared__ float As[16][64];
    __shared__ float Bs[16][64];

    int tid = threadIdx.x;
    int am = tid >> 2, ak4 = (tid & 3) * 4;
    int arow = m_base + am;
    bool avalid = arow < cnt;
    const float* aptr = g_h + (size_t)(avalid ? (off + arow) : 0) * I_DIM + ak4;

    int bk = tid >> 4, bn4 = (tid & 15) * 4;
    const float* bptr = w2 + (size_t)e * I_DIM * H_DIM + (size_t)bk * H_DIM + n_base + bn4;

    int tx = tid & 15, ty = tid >> 4;
    float acc[4][4] = {};

    for (int k0 = 0; k0 < I_DIM; k0 += 16) {
        float4 av = avalid ? *(const float4*)(aptr + k0) : make_float4(0, 0, 0, 0);
        As[ak4 + 0][am] = av.x; As[ak4 + 1][am] = av.y;
        As[ak4 + 2][am] = av.z; As[ak4 + 3][am] = av.w;
        float4 bv = *(const float4*)(bptr + (size_t)k0 * H_DIM);
        *(float4*)&Bs[bk][bn4] = bv;
        __syncthreads();
        #pragma unroll
        for (int k = 0; k < 16; k++) {
            float4 a = *(const float4*)&As[k][ty << 2];
            float4 b = *(const float4*)&Bs[k][tx << 2];
            float ar[4] = {a.x, a.y, a.z, a.w};
            float br[4] = {b.x, b.y, b.z, b.w};
            #pragma unroll
            for (int i = 0; i < 4; i++)
                #pragma unroll
                for (int j = 0; j < 4; j++)
                    acc[i][j] = fmaf(ar[i], br[j], acc[i][j]);
        }
        __syncthreads();
    }

    #pragma unroll
    for (int i = 0; i < 4; i++) {
        int r = m_base + (ty << 2) + i;
        if (r >= cnt) continue;
        int tok = g_list_tok[off + r];
        float w = g_list_w[off + r];
        #pragma unroll
        for (int j = 0; j < 4; j++) {
            int n = n_base + (tx << 2) + j;
            float v = w * (acc[i][j] + b2[e * H_DIM + n]);
            atomicAdd(&out[(size_t)tok * H_DIM + n], v);
        }
    }
}

// ---------------- launch ------------------------------------------------------
extern "C" void kernel_launch(void* const* d_in, const int* in_sizes, int n_in,
                              void* d_out, int out_size) {
    const float* x   = (const float*)d_in[0];
    const float* gw  = (const float*)d_in[1];
    const float* w1  = (const float*)d_in[2];
    const float* b1  = (const float*)d_in[3];
    const float* w2  = (const float*)d_in[4];
    const float* b2  = (const float*)d_in[5];
    float* out = (float*)d_out;
    float* logits = out + (size_t)T_TOKENS * H_DIM;

    zero_small_kernel<<<1, 32>>>();

    int n4 = (T_TOKENS * H_DIM) / 4;
    zero_out_kernel<<<(n4 + 255) / 256, 256>>>((float4*)out, n4);

    router_kernel<<<T_TOKENS / 8, 256>>>(x, gw, logits);
    scan_kernel<<<1, 1>>>();
    scatter_kernel<<<T_TOKENS / 256, 256>>>();

    dim3 g1(I_DIM / 64, T_TOKENS / 64, E_NUM);
    gemm1_kernel<<<g1, 256>>>(x, w1, b1);

    dim3 g2(H_DIM / 64, T_TOKENS / 64, E_NUM);
    gemm2_kernel<<<g2, 256>>>(w2, b2, out);
}

// round 3
// speedup vs baseline: 1.9340x; 1.9340x over previous
#include <cuda_runtime.h>
#include <cuda_bf16.h>
#include <cstdint>
#include <math.h>

#define T_TOKENS 8192
#define H_DIM    512
#define I_DIM    1024
#define E_NUM    8
#define NP       (T_TOKENS * 2)

// ---------------- smem layout for GEMM kernels --------------------------------
// per stage: 4 tiles (AHI, ALO, BHI, BLO), each 128 rows x 32 bf16, padded row
// stride 80 bytes (64B data + 16B pad) -> conflict-free ldmatrix.
#define ROWB      80
#define TILE_SZ   (128 * ROWB)          // 10240 B
#define OFF_AHI   0
#define OFF_ALO   (1 * TILE_SZ)
#define OFF_BHI   (2 * TILE_SZ)
#define OFF_BLO   (3 * TILE_SZ)
#define STG_BYTES (4 * TILE_SZ)         // 40960 B
#define NSTAGE    3
#define SMEM_BYTES (NSTAGE * STG_BYTES) // 122880 B

// ---------------- PTX helpers ---------------------------------------------------
__device__ __forceinline__ uint32_t smem_to_u32(const void* p) {
    uint32_t a;
    asm("{ .reg .u64 t; cvta.to.shared.u64 t, %1; cvt.u32.u64 %0, t; }" : "=r"(a) : "l"(p));
    return a;
}
__device__ __forceinline__ void cp16(uint32_t s, const void* g) {
    asm volatile("cp.async.cg.shared.global [%0], [%1], 16;" :: "r"(s), "l"(g));
}
#define CP_COMMIT() asm volatile("cp.async.commit_group;" ::: "memory")
#define CP_WAIT2()  asm volatile("cp.async.wait_group 2;" ::: "memory")

__device__ __forceinline__ void ldsm4(uint32_t* r, uint32_t a) {
    asm volatile("ldmatrix.sync.aligned.m8n8.x4.shared.b16 {%0,%1,%2,%3}, [%4];"
        : "=r"(r[0]), "=r"(r[1]), "=r"(r[2]), "=r"(r[3]) : "r"(a));
}
__device__ __forceinline__ void mma_bf16(float* c, const uint32_t* a, const uint32_t* b) {
    asm volatile("mma.sync.aligned.m16n8k16.row.col.f32.bf16.bf16.f32 "
        "{%0,%1,%2,%3}, {%4,%5,%6,%7}, {%8,%9}, {%0,%1,%2,%3};"
        : "+f"(c[0]), "+f"(c[1]), "+f"(c[2]), "+f"(c[3])
        : "r"(a[0]), "r"(a[1]), "r"(a[2]), "r"(a[3]), "r"(b[0]), "r"(b[1]));
}

// ---------------- scratch (device globals) -------------------------------------
__device__ int   g_count[E_NUM];
__device__ int   g_cursor[E_NUM];
__device__ int   g_off[E_NUM + 1];
__device__ int   g_tok_e[T_TOKENS * 2];
__device__ float g_tok_w[T_TOKENS * 2];
__device__ int   g_list_tok[NP];
__device__ float g_list_w[NP];
__device__ int   g_pair_idx[T_TOKENS * 2];

__device__ __nv_bfloat16 g_xhi[(size_t)T_TOKENS * H_DIM];
__device__ __nv_bfloat16 g_xlo[(size_t)T_TOKENS * H_DIM];
__device__ __nv_bfloat16 g_w1t_hi[(size_t)E_NUM * I_DIM * H_DIM];   // [e][n=I][k=H]
__device__ __nv_bfloat16 g_w1t_lo[(size_t)E_NUM * I_DIM * H_DIM];
__device__ __nv_bfloat16 g_w2t_hi[(size_t)E_NUM * H_DIM * I_DIM];   // [e][n=H][k=I]
__device__ __nv_bfloat16 g_w2t_lo[(size_t)E_NUM * H_DIM * I_DIM];
__device__ __nv_bfloat16 g_hhi[(size_t)NP * I_DIM];
__device__ __nv_bfloat16 g_hlo[(size_t)NP * I_DIM];
__device__ float         g_y[(size_t)NP * H_DIM];

// ---------------- tiny kernels ---------------------------------------------------
__global__ void zero_small_kernel() {
    int i = threadIdx.x;
    if (i < E_NUM) { g_count[i] = 0; g_cursor[i] = 0; }
}

__global__ void router_kernel(const float* __restrict__ x,
                              const float* __restrict__ gw,
                              float* __restrict__ logits_out) {
    __shared__ int s_cnt[E_NUM];
    int tid = threadIdx.x;
    if (tid < E_NUM) s_cnt[tid] = 0;
    __syncthreads();

    int warp = tid >> 5, lane = tid & 31;
    int t = blockIdx.x * 8 + warp;
    if (t < T_TOKENS) {
        float xr[16];
        #pragma unroll
        for (int j = 0; j < 16; j++) xr[j] = x[(size_t)t * H_DIM + lane + 32 * j];
        float lg[E_NUM];
        #pragma unroll
        for (int e = 0; e < E_NUM; e++) {
            float s = 0.f;
            const float* g = gw + (size_t)e * H_DIM + lane;
            #pragma unroll
            for (int j = 0; j < 16; j++) s = fmaf(xr[j], g[32 * j], s);
            #pragma unroll
            for (int o = 16; o; o >>= 1) s += __shfl_xor_sync(0xffffffffu, s, o);
            lg[e] = s;
        }
        if (lane == 0) {
            float m = lg[0];
            #pragma unroll
            for (int e = 1; e < E_NUM; e++) m = fmaxf(m, lg[e]);
            float p[E_NUM], sum = 0.f;
            #pragma unroll
            for (int e = 0; e < E_NUM; e++) { p[e] = expf(lg[e] - m); sum += p[e]; }
            float inv = 1.f / sum;
            #pragma unroll
            for (int e = 0; e < E_NUM; e++) {
                p[e] *= inv;
                logits_out[(size_t)t * E_NUM + e] = lg[e];
            }
            int i0 = 0;
            #pragma unroll
            for (int e = 1; e < E_NUM; e++) if (p[e] > p[i0]) i0 = e;
            int i1 = (i0 == 0) ? 1 : 0;
            #pragma unroll
            for (int e = 0; e < E_NUM; e++) if (e != i1 && e != i0 && p[e] > p[i1]) i1 = e;
            float w0 = p[i0], w1 = p[i1];
            float s2 = w0 + w1 + 1e-20f;
            w0 = (w0 / s2) * 0.5f;
            w1 = (w1 / s2) * 0.5f;
            g_tok_e[t * 2 + 0] = i0;  g_tok_w[t * 2 + 0] = w0;
            g_tok_e[t * 2 + 1] = i1;  g_tok_w[t * 2 + 1] = w1;
            atomicAdd(&s_cnt[i0], 1);
            atomicAdd(&s_cnt[i1], 1);
        }
    }
    __syncthreads();
    if (tid < E_NUM && s_cnt[tid]) atomicAdd(&g_count[tid], s_cnt[tid]);
}

__global__ void scan_kernel() {
    int o = 0;
    for (int e = 0; e < E_NUM; e++) { g_off[e] = o; o += g_count[e]; }
    g_off[E_NUM] = o;
}

__global__ void scatter_kernel() {
    int t = blockIdx.x * 256 + threadIdx.x;
    if (t >= T_TOKENS) return;
    #pragma unroll
    for (int k = 0; k < 2; k++) {
        int e = g_tok_e[t * 2 + k];
        int pos = atomicAdd(&g_cursor[e], 1);
        int idx = g_off[e] + pos;
        g_list_tok[idx] = t;
        g_list_w[idx]   = g_tok_w[t * 2 + k];
        g_pair_idx[t * 2 + k] = idx;
    }
}

// fp32 -> (hi, lo) bf16 split
__device__ __forceinline__ void split2(float v0, float v1, uint32_t& hw, uint32_t& lw) {
    __nv_bfloat162 h = __floats2bfloat162_rn(v0, v1);
    float r0 = v0 - __bfloat162float(h.x);
    float r1 = v1 - __bfloat162float(h.y);
    __nv_bfloat162 l = __floats2bfloat162_rn(r0, r1);
    hw = *reinterpret_cast<uint32_t*>(&h);
    lw = *reinterpret_cast<uint32_t*>(&l);
}

__global__ void xconv_kernel(const float* __restrict__ x) {
    int i = blockIdx.x * 256 + threadIdx.x;       // over T*H/4
    const float4 v = reinterpret_cast<const float4*>(x)[i];
    uint2 hw, lw;
    split2(v.x, v.y, hw.x, lw.x);
    split2(v.z, v.w, hw.y, lw.y);
    reinterpret_cast<uint2*>(g_xhi)[i] = hw;
    reinterpret_cast<uint2*>(g_xlo)[i] = lw;
}

__device__ __forceinline__ void wconv_body(const float* __restrict__ W,
                                           __nv_bfloat16* __restrict__ whi,
                                           __nv_bfloat16* __restrict__ wlo,
                                           int K, int N) {
    __shared__ float s[32][33];
    int e = blockIdx.z;
    int k0 = blockIdx.y * 32, n0 = blockIdx.x * 32;
    const float* src = W + (size_t)e * K * N;
    int tx = threadIdx.x, ty = threadIdx.y;
    #pragma unroll
    for (int i = 0; i < 4; i++)
        s[ty + 8 * i][tx] = src[(size_t)(k0 + ty + 8 * i) * N + n0 + tx];
    __syncthreads();
    size_t ob = (size_t)e * N * K;
    #pragma unroll
    for (int i = 0; i < 4; i++) {
        int n = n0 + ty + 8 * i;
        float v = s[tx][ty + 8 * i];
        __nv_bfloat16 h = __float2bfloat16(v);
        float r = v - __bfloat162float(h);
        __nv_bfloat16 l = __float2bfloat16(r);
        whi[ob + (size_t)n * K + k0 + tx] = h;
        wlo[ob + (size_t)n * K + k0 + tx] = l;
    }
}
__global__ void wconv1_kernel(const float* __restrict__ W) { wconv_body(W, g_w1t_hi, g_w1t_lo, H_DIM, I_DIM); }
__global__ void wconv2_kernel(const float* __restrict__ W) { wconv_body(W, g_w2t_hi, g_w2t_lo, I_DIM, H_DIM); }

// ---------------- GEMM core (shared between gemm1 / gemm2) ----------------------
// block tile 128(M) x 128(N), KC=32 per stage, 8 warps: wm = w&1 (64M), wn = w>>1 (32N)
struct LoadCtx {
    const char *aHi, *aLo, *bHi, *bLo;   // row base pointers for this thread's row
    uint32_t sRow;                        // rowIdx*80 + (tid&1)*32
    uint32_t gOff;                        // (tid&1)*32 (byte offset into row)
    uint32_t smem0;                       // smem u32 base
};

__device__ __forceinline__ void issue_stage(const LoadCtx& L, int s, int k0elem) {
    uint32_t sb = L.smem0 + s * STG_BYTES + L.sRow;
    size_t gk = (size_t)k0elem * 2 + L.gOff;
    cp16(sb + OFF_AHI,      L.aHi + gk);
    cp16(sb + OFF_AHI + 16, L.aHi + gk + 16);
    cp16(sb + OFF_ALO,      L.aLo + gk);
    cp16(sb + OFF_ALO + 16, L.aLo + gk + 16);
    cp16(sb + OFF_BHI,      L.bHi + gk);
    cp16(sb + OFF_BHI + 16, L.bHi + gk + 16);
    cp16(sb + OFF_BLO,      L.bLo + gk);
    cp16(sb + OFF_BLO + 16, L.bLo + gk + 16);
}

__device__ __forceinline__ void compute_stage(uint32_t sb,
        const uint32_t* aOff, const uint32_t* bOff, float acc[4][4][4]) {
    #pragma unroll
    for (int ks = 0; ks < 2; ks++) {
        uint32_t ah[4][4], al[4][4], bh[2][4], bl[2][4];
        #pragma unroll
        for (int mi = 0; mi < 4; mi++) {
            ldsm4(ah[mi], sb + OFF_AHI + aOff[mi] + ks * 32);
            ldsm4(al[mi], sb + OFF_ALO + aOff[mi] + ks * 32);
        }
        #pragma unroll
        for (int nt = 0; nt < 2; nt++) {
            ldsm4(bh[nt], sb + OFF_BHI + bOff[nt] + ks * 32);
            ldsm4(bl[nt], sb + OFF_BLO + bOff[nt] + ks * 32);
        }
        #pragma unroll
        for (int mi = 0; mi < 4; mi++) {
            #pragma unroll
            for (int ni = 0; ni < 4; ni++) {
                int nt = ni >> 1, j = ni & 1;
                uint32_t bhf[2] = { bh[nt][j], bh[nt][j + 2] };
                uint32_t blf[2] = { bl[nt][j], bl[nt][j + 2] };
                mma_bf16(acc[mi][ni], ah[mi], bhf);
                mma_bf16(acc[mi][ni], ah[mi], blf);
                mma_bf16(acc[mi][ni], al[mi], bhf);
            }
        }
    }
}

// ---------------- GEMM1: h = relu(gather(x) @ W1[e]^T_layout + b1) -> hi/lo ------
__global__ __launch_bounds__(256, 1) void gemm1_kernel(const float* __restrict__ b1) {
    extern __shared__ char smem[];
    const int e = blockIdx.z;
    const int cnt = g_count[e];
    const int m_base = blockIdx.y * 128;
    if (m_base >= cnt) return;
    const int off = g_off[e];
    const int n_base = blockIdx.x * 128;
    const int tid = threadIdx.x;
    const int w = tid >> 5, lane = tid & 31;
    const int wm = w & 1, wn = w >> 1;

    // loader setup: one row (A and B) + 2 chunks per thread
    LoadCtx L;
    {
        int rowIdx = tid >> 1;
        int gm = m_base + rowIdx;
        int tok = g_list_tok[off + ((gm < cnt) ? gm : 0)];
        L.aHi = (const char*)(g_xhi + (size_t)tok * H_DIM);
        L.aLo = (const char*)(g_xlo + (size_t)tok * H_DIM);
        size_t rB = ((size_t)e * I_DIM + (n_base + rowIdx)) * H_DIM;
        L.bHi = (const char*)(g_w1t_hi + rB);
        L.bLo = (const char*)(g_w1t_lo + rB);
        L.gOff = (tid & 1) * 32;
        L.sRow = (uint32_t)rowIdx * ROWB + L.gOff;
        L.smem0 = smem_to_u32(smem);
    }

    // ldmatrix lane offsets
    uint32_t aOff[4], bOff[2];
    {
        int mat = lane >> 3, lr = lane & 7;
        uint32_t kb = (uint32_t)(lane >> 4) * 16;
        #pragma unroll
        for (int mi = 0; mi < 4; mi++)
            aOff[mi] = (uint32_t)(wm * 64 + mi * 16 + ((mat & 1) << 3) + lr) * ROWB + kb;
        #pragma unroll
        for (int nt = 0; nt < 2; nt++)
            bOff[nt] = (uint32_t)(wn * 32 + nt * 16 + ((mat & 1) << 3) + lr) * ROWB + kb;
    }

    float acc[4][4][4] = {};

    const int NC = H_DIM / 32;   // 16
    issue_stage(L, 0, 0);  CP_COMMIT();
    issue_stage(L, 1, 32); CP_COMMIT();
    issue_stage(L, 2, 64); CP_COMMIT();

    for (int c = 0; c < NC; c++) {
        CP_WAIT2();
        __syncthreads();
        compute_stage(L.smem0 + (c % NSTAGE) * STG_BYTES, aOff, bOff, acc);
        __syncthreads();
        if (c + 3 < NC) issue_stage(L, c % NSTAGE, (c + 3) * 32);
        CP_COMMIT();
    }

    // epilogue: bias + relu + split -> g_hhi/g_hlo
    int qrow = lane >> 2, qcol = (lane & 3) * 2;
    #pragma unroll
    for (int mi = 0; mi < 4; mi++) {
        #pragma unroll
        for (int half = 0; half < 2; half++) {
            int row = wm * 64 + mi * 16 + qrow + half * 8;
            int gm = m_base + row;
            if (gm >= cnt) continue;
            size_t pair = (size_t)(off + gm);
            #pragma unroll
            for (int ni = 0; ni < 4; ni++) {
                int n = n_base + wn * 32 + ni * 8 + qcol;
                float v0 = fmaxf(acc[mi][ni][half * 2 + 0] + b1[e * I_DIM + n],     0.f);
                float v1 = fmaxf(acc[mi][ni][half * 2 + 1] + b1[e * I_DIM + n + 1], 0.f);
                uint32_t hw, lw;
                split2(v0, v1, hw, lw);
                *reinterpret_cast<uint32_t*>(g_hhi + pair * I_DIM + n) = hw;
                *reinterpret_cast<uint32_t*>(g_hlo + pair * I_DIM + n) = lw;
            }
        }
    }
}

// ---------------- GEMM2: y = wgt * (h @ W2[e] + b2) ------------------------------
__global__ __launch_bounds__(256, 1) void gemm2_kernel(const float* __restrict__ b2) {
    extern __shared__ char smem[];
    const int e = blockIdx.z;
    const int cnt = g_count[e];
    const int m_base = blockIdx.y * 128;
    if (m_base >= cnt) return;
    const int off = g_off[e];
    const int n_base = blockIdx.x * 128;
    const int tid = threadIdx.x;
    const int w = tid >> 5, lane = tid & 31;
    const int wm = w & 1, wn = w >> 1;

    LoadCtx L;
    {
        int rowIdx = tid >> 1;
        int gm = m_base + rowIdx;
        size_t pr = (size_t)(off + ((gm < cnt) ? gm : 0));
        L.aHi = (const char*)(g_hhi + pr * I_DIM);
        L.aLo = (const char*)(g_hlo + pr * I_DIM);
        size_t rB = ((size_t)e * H_DIM + (n_base + rowIdx)) * I_DIM;
        L.bHi = (const char*)(g_w2t_hi + rB);
        L.bLo = (const char*)(g_w2t_lo + rB);
        L.gOff = (tid & 1) * 32;
        L.sRow = (uint32_t)rowIdx * ROWB + L.gOff;
        L.smem0 = smem_to_u32(smem);
    }

    uint32_t aOff[4], bOff[2];
    {
        int mat = lane >> 3, lr = lane & 7;
        uint32_t kb = (uint32_t)(lane >> 4) * 16;
        #pragma unroll
        for (int mi = 0; mi < 4; mi++)
            aOff[mi] = (uint32_t)(wm * 64 + mi * 16 + ((mat & 1) << 3) + lr) * ROWB + kb;
        #pragma unroll
        for (int nt = 0; nt < 2; nt++)
            bOff[nt] = (uint32_t)(wn * 32 + nt * 16 + ((mat & 1) << 3) + lr) * ROWB + kb;
    }

    float acc[4][4][4] = {};

    const int NC = I_DIM / 32;   // 32
    issue_stage(L, 0, 0);  CP_COMMIT();
    issue_stage(L, 1, 32); CP_COMMIT();
    issue_stage(L, 2, 64); CP_COMMIT();

    for (int c = 0; c < NC; c++) {
        CP_WAIT2();
        __syncthreads();
        compute_stage(L.smem0 + (c % NSTAGE) * STG_BYTES, aOff, bOff, acc);
        __syncthreads();
        if (c + 3 < NC) issue_stage(L, c % NSTAGE, (c + 3) * 32);
        CP_COMMIT();
    }

    int qrow = lane >> 2, qcol = (lane & 3) * 2;
    #pragma unroll
    for (int mi = 0; mi < 4; mi++) {
        #pragma unroll
        for (int half = 0; half < 2; half++) {
            int row = wm * 64 + mi * 16 + qrow + half * 8;
            int gm = m_base + row;
            if (gm >= cnt) continue;
            size_t pair = (size_t)(off + gm);
            float wgt = g_list_w[off + gm];
            #pragma unroll
            for (int ni = 0; ni < 4; ni++) {
                int n = n_base + wn * 32 + ni * 8 + qcol;
                float2 v;
                v.x = wgt * (acc[mi][ni][half * 2 + 0] + b2[e * H_DIM + n]);
                v.y = wgt * (acc[mi][ni][half * 2 + 1] + b2[e * H_DIM + n + 1]);
                *reinterpret_cast<float2*>(g_y + pair * H_DIM + n) = v;
            }
        }
    }
}

// ---------------- combine: out[t] = y[pair0] + y[pair1] --------------------------
__global__ void combine_kernel(float* __restrict__ out) {
    int idx = blockIdx.x * 256 + threadIdx.x;     // over T*H/4
    int t = idx >> 7;                             // H/4 = 128
    int q = idx & 127;
    int i0 = g_pair_idx[t * 2 + 0];
    int i1 = g_pair_idx[t * 2 + 1];
    const float4* y4 = reinterpret_cast<const float4*>(g_y);
    float4 a = y4[(size_t)i0 * 128 + q];
    float4 b = y4[(size_t)i1 * 128 + q];
    reinterpret_cast<float4*>(out)[idx] =
        make_float4(a.x + b.x, a.y + b.y, a.z + b.z, a.w + b.w);
}

// ---------------- launch ----------------------------------------------------------
extern "C" void kernel_launch(void* const* d_in, const int* in_sizes, int n_in,
                              void* d_out, int out_size) {
    const float* x  = (const float*)d_in[0];
    const float* gw = (const float*)d_in[1];
    const float* w1 = (const float*)d_in[2];
    const float* b1 = (const float*)d_in[3];
    const float* w2 = (const float*)d_in[4];
    const float* b2 = (const float*)d_in[5];
    float* out = (float*)d_out;
    float* logits = out + (size_t)T_TOKENS * H_DIM;

    cudaFuncSetAttribute(gemm1_kernel, cudaFuncAttributeMaxDynamicSharedMemorySize, SMEM_BYTES);
    cudaFuncSetAttribute(gemm2_kernel, cudaFuncAttributeMaxDynamicSharedMemorySize, SMEM_BYTES);

    zero_small_kernel<<<1, 32>>>();
    router_kernel<<<T_TOKENS / 8, 256>>>(x, gw, logits);
    scan_kernel<<<1, 1>>>();
    scatter_kernel<<<T_TOKENS / 256, 256>>>();

    xconv_kernel<<<(T_TOKENS * H_DIM / 4) / 256, 256>>>(x);
    wconv1_kernel<<<dim3(I_DIM / 32, H_DIM / 32, E_NUM), dim3(32, 8)>>>(w1);
    wconv2_kernel<<<dim3(H_DIM / 32, I_DIM / 32, E_NUM), dim3(32, 8)>>>(w2);

    dim3 g1(I_DIM / 128, T_TOKENS / 128, E_NUM);
    gemm1_kernel<<<g1, 256, SMEM_BYTES>>>(b1);

    dim3 g2(H_DIM / 128, T_TOKENS / 128, E_NUM);
    gemm2_kernel<<<g2, 256, SMEM_BYTES>>>(b2);

    combine_kernel<<<(T_TOKENS * H_DIM / 4) / 256, 256>>>(out);
}

// round 4
// speedup vs baseline: 2.1982x; 1.1366x over previous
#include <cuda_runtime.h>
#include <cuda_bf16.h>
#include <cstdint>
#include <math.h>

#define T_TOKENS 8192
#define H_DIM    512
#define I_DIM    1024
#define E_NUM    8
#define NP       (T_TOKENS * 2)
#define KC       64                      // K elems per stage (128B rows)

// ---------------- smem layout -------------------------------------------------
// per stage: 4 tiles (AHI, ALO, BHI, BLO), each 128 rows x 64 bf16,
// row stride 144B (128B data + 16B pad) -> conflict-free ldmatrix.
#define ROWB      144
#define TILE_SZ   (128 * ROWB)           // 18432 B
#define OFF_AHI   0
#define OFF_ALO   (1 * TILE_SZ)
#define OFF_BHI   (2 * TILE_SZ)
#define OFF_BLO   (3 * TILE_SZ)
#define STG_BYTES (4 * TILE_SZ)          // 73728 B
#define SMEM_BYTES (2 * STG_BYTES)       // 147456 B (double buffer)

// ---------------- PTX helpers ---------------------------------------------------
__device__ __forceinline__ uint32_t smem_to_u32(const void* p) {
    uint32_t a;
    asm("{ .reg .u64 t; cvta.to.shared.u64 t, %1; cvt.u32.u64 %0, t; }" : "=r"(a) : "l"(p));
    return a;
}
__device__ __forceinline__ void cp16(uint32_t s, const void* g) {
    asm volatile("cp.async.cg.shared.global [%0], [%1], 16;" :: "r"(s), "l"(g));
}
#define CP_COMMIT() asm volatile("cp.async.commit_group;" ::: "memory")
#define CP_WAIT1()  asm volatile("cp.async.wait_group 1;" ::: "memory")
#define CP_WAIT0()  asm volatile("cp.async.wait_group 0;" ::: "memory")

__device__ __forceinline__ void ldsm4(uint32_t* r, uint32_t a) {
    asm volatile("ldmatrix.sync.aligned.m8n8.x4.shared.b16 {%0,%1,%2,%3}, [%4];"
        : "=r"(r[0]), "=r"(r[1]), "=r"(r[2]), "=r"(r[3]) : "r"(a));
}
__device__ __forceinline__ void mma_bf16(float* c, const uint32_t* a, const uint32_t* b) {
    asm volatile("mma.sync.aligned.m16n8k16.row.col.f32.bf16.bf16.f32 "
        "{%0,%1,%2,%3}, {%4,%5,%6,%7}, {%8,%9}, {%0,%1,%2,%3};"
        : "+f"(c[0]), "+f"(c[1]), "+f"(c[2]), "+f"(c[3])
        : "r"(a[0]), "r"(a[1]), "r"(a[2]), "r"(a[3]), "r"(b[0]), "r"(b[1]));
}

// ---------------- scratch (device globals) -------------------------------------
__device__ int   g_count[E_NUM];
__device__ int   g_cursor[E_NUM];
__device__ int   g_off[E_NUM + 1];
__device__ int   g_tok_e[T_TOKENS * 2];
__device__ float g_tok_w[T_TOKENS * 2];
__device__ int   g_list_tok[NP];
__device__ float g_list_w[NP];

__device__ __nv_bfloat16 g_xhi[(size_t)T_TOKENS * H_DIM];
__device__ __nv_bfloat16 g_xlo[(size_t)T_TOKENS * H_DIM];
__device__ __nv_bfloat16 g_w1t_hi[(size_t)E_NUM * I_DIM * H_DIM];   // [e][n=I][k=H]
__device__ __nv_bfloat16 g_w1t_lo[(size_t)E_NUM * I_DIM * H_DIM];
__device__ __nv_bfloat16 g_w2t_hi[(size_t)E_NUM * H_DIM * I_DIM];   // [e][n=H][k=I]
__device__ __nv_bfloat16 g_w2t_lo[(size_t)E_NUM * H_DIM * I_DIM];
__device__ __nv_bfloat16 g_hhi[(size_t)NP * I_DIM];
__device__ __nv_bfloat16 g_hlo[(size_t)NP * I_DIM];

// ---------------- tiny kernels ---------------------------------------------------
__global__ void zero_small_kernel() {
    int i = threadIdx.x;
    if (i < E_NUM) { g_count[i] = 0; g_cursor[i] = 0; }
}

__global__ void zero_out_kernel(float4* __restrict__ out4) {
    int i = blockIdx.x * 256 + threadIdx.x;
    out4[i] = make_float4(0.f, 0.f, 0.f, 0.f);
}

__global__ void router_kernel(const float* __restrict__ x,
                              const float* __restrict__ gw,
                              float* __restrict__ logits_out) {
    __shared__ int s_cnt[E_NUM];
    int tid = threadIdx.x;
    if (tid < E_NUM) s_cnt[tid] = 0;
    __syncthreads();

    int warp = tid >> 5, lane = tid & 31;
    int t = blockIdx.x * 8 + warp;
    if (t < T_TOKENS) {
        float xr[16];
        #pragma unroll
        for (int j = 0; j < 16; j++) xr[j] = x[(size_t)t * H_DIM + lane + 32 * j];
        float lg[E_NUM];
        #pragma unroll
        for (int e = 0; e < E_NUM; e++) {
            float s = 0.f;
            const float* g = gw + (size_t)e * H_DIM + lane;
            #pragma unroll
            for (int j = 0; j < 16; j++) s = fmaf(xr[j], g[32 * j], s);
            #pragma unroll
            for (int o = 16; o; o >>= 1) s += __shfl_xor_sync(0xffffffffu, s, o);
            lg[e] = s;
        }
        if (lane == 0) {
            float m = lg[0];
            #pragma unroll
            for (int e = 1; e < E_NUM; e++) m = fmaxf(m, lg[e]);
            float p[E_NUM], sum = 0.f;
            #pragma unroll
            for (int e = 0; e < E_NUM; e++) { p[e] = expf(lg[e] - m); sum += p[e]; }
            float inv = 1.f / sum;
            #pragma unroll
            for (int e = 0; e < E_NUM; e++) {
                p[e] *= inv;
                logits_out[(size_t)t * E_NUM + e] = lg[e];
            }
            int i0 = 0;
            #pragma unroll
            for (int e = 1; e < E_NUM; e++) if (p[e] > p[i0]) i0 = e;
            int i1 = (i0 == 0) ? 1 : 0;
            #pragma unroll
            for (int e = 0; e < E_NUM; e++) if (e != i1 && e != i0 && p[e] > p[i1]) i1 = e;
            float w0 = p[i0], w1 = p[i1];
            float s2 = w0 + w1 + 1e-20f;
            w0 = (w0 / s2) * 0.5f;
            w1 = (w1 / s2) * 0.5f;
            g_tok_e[t * 2 + 0] = i0;  g_tok_w[t * 2 + 0] = w0;
            g_tok_e[t * 2 + 1] = i1;  g_tok_w[t * 2 + 1] = w1;
            atomicAdd(&s_cnt[i0], 1);
            atomicAdd(&s_cnt[i1], 1);
        }
    }
    __syncthreads();
    if (tid < E_NUM && s_cnt[tid]) atomicAdd(&g_count[tid], s_cnt[tid]);
}

__global__ void scan_kernel() {
    int o = 0;
    for (int e = 0; e < E_NUM; e++) { g_off[e] = o; o += g_count[e]; }
    g_off[E_NUM] = o;
}

__global__ void scatter_kernel() {
    int t = blockIdx.x * 256 + threadIdx.x;
    if (t >= T_TOKENS) return;
    #pragma unroll
    for (int k = 0; k < 2; k++) {
        int e = g_tok_e[t * 2 + k];
        int pos = atomicAdd(&g_cursor[e], 1);
        int idx = g_off[e] + pos;
        g_list_tok[idx] = t;
        g_list_w[idx]   = g_tok_w[t * 2 + k];
    }
}

// fp32 -> (hi, lo) bf16 split
__device__ __forceinline__ void split2(float v0, float v1, uint32_t& hw, uint32_t& lw) {
    __nv_bfloat162 h = __floats2bfloat162_rn(v0, v1);
    float r0 = v0 - __bfloat162float(h.x);
    float r1 = v1 - __bfloat162float(h.y);
    __nv_bfloat162 l = __floats2bfloat162_rn(r0, r1);
    hw = *reinterpret_cast<uint32_t*>(&h);
    lw = *reinterpret_cast<uint32_t*>(&l);
}

__global__ void xconv_kernel(const float* __restrict__ x) {
    int i = blockIdx.x * 256 + threadIdx.x;       // over T*H/4
    const float4 v = reinterpret_cast<const float4*>(x)[i];
    uint2 hw, lw;
    split2(v.x, v.y, hw.x, lw.x);
    split2(v.z, v.w, hw.y, lw.y);
    reinterpret_cast<uint2*>(g_xhi)[i] = hw;
    reinterpret_cast<uint2*>(g_xlo)[i] = lw;
}

__device__ __forceinline__ void wconv_body(const float* __restrict__ W,
                                           __nv_bfloat16* __restrict__ whi,
                                           __nv_bfloat16* __restrict__ wlo,
                                           int K, int N) {
    __shared__ float s[32][33];
    int e = blockIdx.z;
    int k0 = blockIdx.y * 32, n0 = blockIdx.x * 32;
    const float* src = W + (size_t)e * K * N;
    int tx = threadIdx.x, ty = threadIdx.y;
    #pragma unroll
    for (int i = 0; i < 4; i++)
        s[ty + 8 * i][tx] = src[(size_t)(k0 + ty + 8 * i) * N + n0 + tx];
    __syncthreads();
    size_t ob = (size_t)e * N * K;
    #pragma unroll
    for (int i = 0; i < 4; i++) {
        int n = n0 + ty + 8 * i;
        float v = s[tx][ty + 8 * i];
        __nv_bfloat16 h = __float2bfloat16(v);
        float r = v - __bfloat162float(h);
        __nv_bfloat16 l = __float2bfloat16(r);
        whi[ob + (size_t)n * K + k0 + tx] = h;
        wlo[ob + (size_t)n * K + k0 + tx] = l;
    }
}
__global__ void wconv1_kernel(const float* __restrict__ W) { wconv_body(W, g_w1t_hi, g_w1t_lo, H_DIM, I_DIM); }
__global__ void wconv2_kernel(const float* __restrict__ W) { wconv_body(W, g_w2t_hi, g_w2t_lo, I_DIM, H_DIM); }

// ---------------- GEMM core ------------------------------------------------------
// block tile 128(M) x 128(N), KC=64/stage, 512 threads (16 warps): warp tile 32x32
struct LoadCtx {
    const char *aHi, *aLo, *bHi, *bLo;   // row base pointers for this thread's row
    uint32_t sRow;                        // rowIdx*ROWB + gOff
    uint32_t gOff;                        // (tid&3)*32 bytes within 128B row chunk
    uint32_t smem0;
};

__device__ __forceinline__ void issue_stage(const LoadCtx& L, int s, int k0elem) {
    uint32_t sb = L.smem0 + s * STG_BYTES + L.sRow;
    size_t gk = (size_t)k0elem * 2 + L.gOff;
    cp16(sb + OFF_AHI,      L.aHi + gk);
    cp16(sb + OFF_AHI + 16, L.aHi + gk + 16);
    cp16(sb + OFF_ALO,      L.aLo + gk);
    cp16(sb + OFF_ALO + 16, L.aLo + gk + 16);
    cp16(sb + OFF_BHI,      L.bHi + gk);
    cp16(sb + OFF_BHI + 16, L.bHi + gk + 16);
    cp16(sb + OFF_BLO,      L.bLo + gk);
    cp16(sb + OFF_BLO + 16, L.bLo + gk + 16);
}

__device__ __forceinline__ void compute_stage(uint32_t sb,
        const uint32_t* aOff, const uint32_t* bOff, float acc[2][4][4]) {
    #pragma unroll
    for (int ks = 0; ks < 4; ks++) {
        uint32_t ah[2][4], al[2][4], bh[2][4], bl[2][4];
        #pragma unroll
        for (int mi = 0; mi < 2; mi++) {
            ldsm4(ah[mi], sb + OFF_AHI + aOff[mi] + ks * 32);
            ldsm4(al[mi], sb + OFF_ALO + aOff[mi] + ks * 32);
        }
        #pragma unroll
        for (int nt = 0; nt < 2; nt++) {
            ldsm4(bh[nt], sb + OFF_BHI + bOff[nt] + ks * 32);
            ldsm4(bl[nt], sb + OFF_BLO + bOff[nt] + ks * 32);
        }
        #pragma unroll
        for (int mi = 0; mi < 2; mi++) {
            #pragma unroll
            for (int ni = 0; ni < 4; ni++) {
                int nt = ni >> 1, j = ni & 1;
                uint32_t bhf[2] = { bh[nt][j], bh[nt][j + 2] };
                uint32_t blf[2] = { bl[nt][j], bl[nt][j + 2] };
                mma_bf16(acc[mi][ni], ah[mi], bhf);
                mma_bf16(acc[mi][ni], ah[mi], blf);
                mma_bf16(acc[mi][ni], al[mi], bhf);
            }
        }
    }
}

// ---------------- GEMM1: h = relu(gather(x) @ W1t + b1) -> hi/lo bf16 ------------
__global__ __launch_bounds__(512, 1) void gemm1_kernel(const float* __restrict__ b1) {
    extern __shared__ char smem[];
    const int e = blockIdx.z;
    const int cnt = g_count[e];
    const int m_base = blockIdx.y * 128;
    if (m_base >= cnt) return;
    const int off = g_off[e];
    const int n_base = blockIdx.x * 128;
    const int tid = threadIdx.x;
    const int w = tid >> 5, lane = tid & 31;
    const int wm = w & 3, wn = w >> 2;

    LoadCtx L;
    {
        int rowIdx = tid >> 2;
        int gm = m_base + rowIdx;
        int tok = g_list_tok[off + ((gm < cnt) ? gm : 0)];
        L.aHi = (const char*)(g_xhi + (size_t)tok * H_DIM);
        L.aLo = (const char*)(g_xlo + (size_t)tok * H_DIM);
        size_t rB = ((size_t)e * I_DIM + (n_base + rowIdx)) * H_DIM;
        L.bHi = (const char*)(g_w1t_hi + rB);
        L.bLo = (const char*)(g_w1t_lo + rB);
        L.gOff = (tid & 3) * 32;
        L.sRow = (uint32_t)rowIdx * ROWB + L.gOff;
        L.smem0 = smem_to_u32(smem);
    }

    uint32_t aOff[2], bOff[2];
    {
        int mat = lane >> 3, lr = lane & 7;
        uint32_t kb = (uint32_t)(lane >> 4) * 16;
        #pragma unroll
        for (int mi = 0; mi < 2; mi++)
            aOff[mi] = (uint32_t)(wm * 32 + mi * 16 + ((mat & 1) << 3) + lr) * ROWB + kb;
        #pragma unroll
        for (int nt = 0; nt < 2; nt++)
            bOff[nt] = (uint32_t)(wn * 32 + nt * 16 + ((mat & 1) << 3) + lr) * ROWB + kb;
    }

    float acc[2][4][4] = {};

    const int NC = H_DIM / KC;   // 8
    issue_stage(L, 0, 0);  CP_COMMIT();
    for (int c = 0; c < NC; c++) {
        if (c + 1 < NC) { issue_stage(L, (c + 1) & 1, (c + 1) * KC); CP_COMMIT(); CP_WAIT1(); }
        else CP_WAIT0();
        __syncthreads();
        compute_stage(L.smem0 + (c & 1) * STG_BYTES, aOff, bOff, acc);
        __syncthreads();
    }

    int qrow = lane >> 2, qcol = (lane & 3) * 2;
    #pragma unroll
    for (int mi = 0; mi < 2; mi++) {
        #pragma unroll
        for (int half = 0; half < 2; half++) {
            int row = wm * 32 + mi * 16 + qrow + half * 8;
            int gm = m_base + row;
            if (gm >= cnt) continue;
            size_t pair = (size_t)(off + gm);
            #pragma unroll
            for (int ni = 0; ni < 4; ni++) {
                int n = n_base + wn * 32 + ni * 8 + qcol;
                float v0 = fmaxf(acc[mi][ni][half * 2 + 0] + b1[e * I_DIM + n],     0.f);
                float v1 = fmaxf(acc[mi][ni][half * 2 + 1] + b1[e * I_DIM + n + 1], 0.f);
                uint32_t hw, lw;
                split2(v0, v1, hw, lw);
                *reinterpret_cast<uint32_t*>(g_hhi + pair * I_DIM + n) = hw;
                *reinterpret_cast<uint32_t*>(g_hlo + pair * I_DIM + n) = lw;
            }
        }
    }
}

// ---------------- GEMM2: out[tok] += wgt * (h @ W2t + b2) (2 atomic adds/elem) ---
__global__ __launch_bounds__(512, 1) void gemm2_kernel(const float* __restrict__ b2,
                                                       float* __restrict__ out) {
    extern __shared__ char smem[];
    const int e = blockIdx.z;
    const int cnt = g_count[e];
    const int m_base = blockIdx.y * 128;
    if (m_base >= cnt) return;
    const int off = g_off[e];
    const int n_base = blockIdx.x * 128;
    const int tid = threadIdx.x;
    const int w = tid >> 5, lane = tid & 31;
    const int wm = w & 3, wn = w >> 2;

    LoadCtx L;
    {
        int rowIdx = tid >> 2;
        int gm = m_base + rowIdx;
        size_t pr = (size_t)(off + ((gm < cnt) ? gm : 0));
        L.aHi = (const char*)(g_hhi + pr * I_DIM);
        L.aLo = (const char*)(g_hlo + pr * I_DIM);
        size_t rB = ((size_t)e * H_DIM + (n_base + rowIdx)) * I_DIM;
        L.bHi = (const char*)(g_w2t_hi + rB);
        L.bLo = (const char*)(g_w2t_lo + rB);
        L.gOff = (tid & 3) * 32;
        L.sRow = (uint32_t)rowIdx * ROWB + L.gOff;
        L.smem0 = smem_to_u32(smem);
    }

    uint32_t aOff[2], bOff[2];
    {
        int mat = lane >> 3, lr = lane & 7;
        uint32_t kb = (uint32_t)(lane >> 4) * 16;
        #pragma unroll
        for (int mi = 0; mi < 2; mi++)
            aOff[mi] = (uint32_t)(wm * 32 + mi * 16 + ((mat & 1) << 3) + lr) * ROWB + kb;
        #pragma unroll
        for (int nt = 0; nt < 2; nt++)
            bOff[nt] = (uint32_t)(wn * 32 + nt * 16 + ((mat & 1) << 3) + lr) * ROWB + kb;
    }

    float acc[2][4][4] = {};

    const int NC = I_DIM / KC;   // 16
    issue_stage(L, 0, 0);  CP_COMMIT();
    for (int c = 0; c < NC; c++) {
        if (c + 1 < NC) { issue_stage(L, (c + 1) & 1, (c + 1) * KC); CP_COMMIT(); CP_WAIT1(); }
        else CP_WAIT0();
        __syncthreads();
        compute_stage(L.smem0 + (c & 1) * STG_BYTES, aOff, bOff, acc);
        __syncthreads();
    }

    int qrow = lane >> 2, qcol = (lane & 3) * 2;
    #pragma unroll
    for (int mi = 0; mi < 2; mi++) {
        #pragma unroll
        for (int half = 0; half < 2; half++) {
            int row = wm * 32 + mi * 16 + qrow + half * 8;
            int gm = m_base + row;
            if (gm >= cnt) continue;
            int tok = g_list_tok[off + gm];
            float wgt = g_list_w[off + gm];
            float* dst = out + (size_t)tok * H_DIM;
            #pragma unroll
            for (int ni = 0; ni < 4; ni++) {
                int n = n_base + wn * 32 + ni * 8 + qcol;
                atomicAdd(&dst[n],     wgt * (acc[mi][ni][half * 2 + 0] + b2[e * H_DIM + n]));
                atomicAdd(&dst[n + 1], wgt * (acc[mi][ni][half * 2 + 1] + b2[e * H_DIM + n + 1]));
            }
        }
    }
}

// ---------------- launch ----------------------------------------------------------
extern "C" void kernel_launch(void* const* d_in, const int* in_sizes, int n_in,
                              void* d_out, int out_size) {
    const float* x  = (const float*)d_in[0];
    const float* gw = (const float*)d_in[1];
    const float* w1 = (const float*)d_in[2];
    const float* b1 = (const float*)d_in[3];
    const float* w2 = (const float*)d_in[4];
    const float* b2 = (const float*)d_in[5];
    float* out = (float*)d_out;
    float* logits = out + (size_t)T_TOKENS * H_DIM;

    cudaFuncSetAttribute(gemm1_kernel, cudaFuncAttributeMaxDynamicSharedMemorySize, SMEM_BYTES);
    cudaFuncSetAttribute(gemm2_kernel, cudaFuncAttributeMaxDynamicSharedMemorySize, SMEM_BYTES);

    zero_small_kernel<<<1, 32>>>();
    zero_out_kernel<<<(T_TOKENS * H_DIM / 4) / 256, 256>>>((float4*)out);
    router_kernel<<<T_TOKENS / 8, 256>>>(x, gw, logits);
    scan_kernel<<<1, 1>>>();
    scatter_kernel<<<T_TOKENS / 256, 256>>>();

    xconv_kernel<<<(T_TOKENS * H_DIM / 4) / 256, 256>>>(x);
    wconv1_kernel<<<dim3(I_DIM / 32, H_DIM / 32, E_NUM), dim3(32, 8)>>>(w1);
    wconv2_kernel<<<dim3(H_DIM / 32, I_DIM / 32, E_NUM), dim3(32, 8)>>>(w2);

    dim3 g1(I_DIM / 128, T_TOKENS / 128, E_NUM);
    gemm1_kernel<<<g1, 512, SMEM_BYTES>>>(b1);

    dim3 g2(H_DIM / 128, T_TOKENS / 128, E_NUM);
    gemm2_kernel<<<g2, 512, SMEM_BYTES>>>(b2, out);
}

// round 5
// speedup vs baseline: 2.2619x; 1.0290x over previous
#include <cuda_runtime.h>
#include <cuda_bf16.h>
#include <cstdint>
#include <math.h>

#define T_TOKENS 8192
#define H_DIM    512
#define I_DIM    1024
#define E_NUM    8
#define NP       (T_TOKENS * 2)
#define KC       64                      // K elems per stage (128B rows)

// ---------------- smem layout -------------------------------------------------
#define ROWB      144
#define TILE_SZ   (128 * ROWB)           // 18432 B
#define OFF_AHI   0
#define OFF_ALO   (1 * TILE_SZ)
#define OFF_BHI   (2 * TILE_SZ)
#define OFF_BLO   (3 * TILE_SZ)
#define STG_BYTES (4 * TILE_SZ)          // 73728 B
#define NSTAGE    3
#define SMEM_BYTES (NSTAGE * STG_BYTES)  // 221184 B

// ---------------- PTX helpers ---------------------------------------------------
__device__ __forceinline__ uint32_t smem_to_u32(const void* p) {
    uint32_t a;
    asm("{ .reg .u64 t; cvta.to.shared.u64 t, %1; cvt.u32.u64 %0, t; }" : "=r"(a) : "l"(p));
    return a;
}
__device__ __forceinline__ void cp16(uint32_t s, const void* g) {
    asm volatile("cp.async.cg.shared.global [%0], [%1], 16;" :: "r"(s), "l"(g));
}
#define CP_COMMIT() asm volatile("cp.async.commit_group;" ::: "memory")
#define CP_WAIT1()  asm volatile("cp.async.wait_group 1;" ::: "memory")
#define CP_WAIT0()  asm volatile("cp.async.wait_group 0;" ::: "memory")

__device__ __forceinline__ void ldsm4(uint32_t* r, uint32_t a) {
    asm volatile("ldmatrix.sync.aligned.m8n8.x4.shared.b16 {%0,%1,%2,%3}, [%4];"
        : "=r"(r[0]), "=r"(r[1]), "=r"(r[2]), "=r"(r[3]) : "r"(a));
}
__device__ __forceinline__ void mma_bf16(float* c, const uint32_t* a, const uint32_t* b) {
    asm volatile("mma.sync.aligned.m16n8k16.row.col.f32.bf16.bf16.f32 "
        "{%0,%1,%2,%3}, {%4,%5,%6,%7}, {%8,%9}, {%0,%1,%2,%3};"
        : "+f"(c[0]), "+f"(c[1]), "+f"(c[2]), "+f"(c[3])
        : "r"(a[0]), "r"(a[1]), "r"(a[2]), "r"(a[3]), "r"(b[0]), "r"(b[1]));
}

// ---------------- scratch (device globals) -------------------------------------
__device__ int   g_count[E_NUM];
__device__ int   g_off[E_NUM + 1];
__device__ int   g_tok_e[T_TOKENS * 2];
__device__ float g_tok_w[T_TOKENS * 2];
__device__ int   g_list_tok[NP];
__device__ float g_list_w[NP];

__device__ __nv_bfloat16 g_xhi[(size_t)T_TOKENS * H_DIM];
__device__ __nv_bfloat16 g_xlo[(size_t)T_TOKENS * H_DIM];
__device__ __nv_bfloat16 g_w1t_hi[(size_t)E_NUM * I_DIM * H_DIM];   // [e][n=I][k=H]
__device__ __nv_bfloat16 g_w1t_lo[(size_t)E_NUM * I_DIM * H_DIM];
__device__ __nv_bfloat16 g_w2t_hi[(size_t)E_NUM * H_DIM * I_DIM];   // [e][n=H][k=I]
__device__ __nv_bfloat16 g_w2t_lo[(size_t)E_NUM * H_DIM * I_DIM];
__device__ __nv_bfloat16 g_hhi[(size_t)NP * I_DIM];
__device__ __nv_bfloat16 g_hlo[(size_t)NP * I_DIM];

// ---------------- router (fused: zero out-head, logits, top-2, x split) ---------
__global__ void router_kernel(const float* __restrict__ x,
                              const float* __restrict__ gw,
                              float* __restrict__ logits_out,
                              float4* __restrict__ out4) {
    int tid = threadIdx.x;
    // zero 16KB of output head per block (1024 blocks x 256 thr x 4 float4 = 16MB)
    #pragma unroll
    for (int i = 0; i < 4; i++)
        out4[(size_t)blockIdx.x * 1024 + i * 256 + tid] = make_float4(0.f, 0.f, 0.f, 0.f);

    int warp = tid >> 5, lane = tid & 31;
    int t = blockIdx.x * 8 + warp;

    float xr[16];
    #pragma unroll
    for (int j = 0; j < 16; j++) xr[j] = x[(size_t)t * H_DIM + lane + 32 * j];

    // fused x split -> bf16 hi/lo
    #pragma unroll
    for (int j = 0; j < 16; j++) {
        __nv_bfloat16 h = __float2bfloat16(xr[j]);
        float r = xr[j] - __bfloat162float(h);
        __nv_bfloat16 l = __float2bfloat16(r);
        g_xhi[(size_t)t * H_DIM + lane + 32 * j] = h;
        g_xlo[(size_t)t * H_DIM + lane + 32 * j] = l;
    }

    float lg[E_NUM];
    #pragma unroll
    for (int e = 0; e < E_NUM; e++) {
        float s = 0.f;
        const float* g = gw + (size_t)e * H_DIM + lane;
        #pragma unroll
        for (int j = 0; j < 16; j++) s = fmaf(xr[j], g[32 * j], s);
        #pragma unroll
        for (int o = 16; o; o >>= 1) s += __shfl_xor_sync(0xffffffffu, s, o);
        lg[e] = s;
    }
    if (lane == 0) {
        float m = lg[0];
        #pragma unroll
        for (int e = 1; e < E_NUM; e++) m = fmaxf(m, lg[e]);
        float p[E_NUM], sum = 0.f;
        #pragma unroll
        for (int e = 0; e < E_NUM; e++) { p[e] = expf(lg[e] - m); sum += p[e]; }
        float inv = 1.f / sum;
        #pragma unroll
        for (int e = 0; e < E_NUM; e++) {
            p[e] *= inv;
            logits_out[(size_t)t * E_NUM + e] = lg[e];
        }
        int i0 = 0;
        #pragma unroll
        for (int e = 1; e < E_NUM; e++) if (p[e] > p[i0]) i0 = e;
        int i1 = (i0 == 0) ? 1 : 0;
        #pragma unroll
        for (int e = 0; e < E_NUM; e++) if (e != i1 && e != i0 && p[e] > p[i1]) i1 = e;
        float w0 = p[i0], w1 = p[i1];
        float s2 = w0 + w1 + 1e-20f;
        w0 = (w0 / s2) * 0.5f;
        w1 = (w1 / s2) * 0.5f;
        g_tok_e[t * 2 + 0] = i0;  g_tok_w[t * 2 + 0] = w0;
        g_tok_e[t * 2 + 1] = i1;  g_tok_w[t * 2 + 1] = w1;
    }
}

// ---------------- scan+scatter (single block, recounts from g_tok_e) ------------
__global__ void scan_scatter_kernel() {
    __shared__ int s_cnt[E_NUM];
    __shared__ int s_cur[E_NUM];
    int tid = threadIdx.x;
    int lane = tid & 31;
    if (tid < E_NUM) s_cnt[tid] = 0;
    __syncthreads();

    int local[E_NUM] = {};
    for (int i = tid; i < NP; i += 1024) {
        int e = g_tok_e[i];
        #pragma unroll
        for (int q = 0; q < E_NUM; q++) local[q] += (e == q);
    }
    #pragma unroll
    for (int q = 0; q < E_NUM; q++) {
        int v = local[q];
        #pragma unroll
        for (int o = 16; o; o >>= 1) v += __shfl_down_sync(0xffffffffu, v, o);
        if (lane == 0 && v) atomicAdd(&s_cnt[q], v);
    }
    __syncthreads();
    if (tid == 0) {
        int o = 0;
        #pragma unroll
        for (int e = 0; e < E_NUM; e++) {
            g_off[e] = o; s_cur[e] = o; o += s_cnt[e];
        }
        g_off[E_NUM] = o;
    }
    __syncthreads();
    if (tid < E_NUM) g_count[tid] = s_cnt[tid];
    for (int i = tid; i < NP; i += 1024) {
        int e = g_tok_e[i];
        int pos = atomicAdd(&s_cur[e], 1);
        g_list_tok[pos] = i >> 1;
        g_list_w[pos]   = g_tok_w[i];
    }
}

// ---------------- weight convert+transpose -> hi/lo bf16 ------------------------
__device__ __forceinline__ void wconv_body(const float* __restrict__ W,
                                           __nv_bfloat16* __restrict__ whi,
                                           __nv_bfloat16* __restrict__ wlo,
                                           int K, int N) {
    __shared__ float s[32][33];
    int e = blockIdx.z;
    int k0 = blockIdx.y * 32, n0 = blockIdx.x * 32;
    const float* src = W + (size_t)e * K * N;
    int tx = threadIdx.x, ty = threadIdx.y;
    #pragma unroll
    for (int i = 0; i < 4; i++)
        s[ty + 8 * i][tx] = src[(size_t)(k0 + ty + 8 * i) * N + n0 + tx];
    __syncthreads();
    size_t ob = (size_t)e * N * K;
    #pragma unroll
    for (int i = 0; i < 4; i++) {
        int n = n0 + ty + 8 * i;
        float v = s[tx][ty + 8 * i];
        __nv_bfloat16 h = __float2bfloat16(v);
        float r = v - __bfloat162float(h);
        __nv_bfloat16 l = __float2bfloat16(r);
        whi[ob + (size_t)n * K + k0 + tx] = h;
        wlo[ob + (size_t)n * K + k0 + tx] = l;
    }
}
__global__ void wconv1_kernel(const float* __restrict__ W) { wconv_body(W, g_w1t_hi, g_w1t_lo, H_DIM, I_DIM); }
__global__ void wconv2_kernel(const float* __restrict__ W) { wconv_body(W, g_w2t_hi, g_w2t_lo, I_DIM, H_DIM); }

// ---------------- GEMM core ------------------------------------------------------
struct LoadCtx {
    const char *aHi, *aLo, *bHi, *bLo;
    uint32_t sRow, gOff, smem0;
};

__device__ __forceinline__ void issue_stage(const LoadCtx& L, int s, int k0elem) {
    uint32_t sb = L.smem0 + s * STG_BYTES + L.sRow;
    size_t gk = (size_t)k0elem * 2 + L.gOff;
    cp16(sb + OFF_AHI,      L.aHi + gk);
    cp16(sb + OFF_AHI + 16, L.aHi + gk + 16);
    cp16(sb + OFF_ALO,      L.aLo + gk);
    cp16(sb + OFF_ALO + 16, L.aLo + gk + 16);
    cp16(sb + OFF_BHI,      L.bHi + gk);
    cp16(sb + OFF_BHI + 16, L.bHi + gk + 16);
    cp16(sb + OFF_BLO,      L.bLo + gk);
    cp16(sb + OFF_BLO + 16, L.bLo + gk + 16);
}

__device__ __forceinline__ void compute_stage(uint32_t sb,
        const uint32_t* aOff, const uint32_t* bOff, float acc[2][4][4]) {
    #pragma unroll
    for (int ks = 0; ks < 4; ks++) {
        uint32_t ah[2][4], al[2][4], bh[2][4], bl[2][4];
        #pragma unroll
        for (int mi = 0; mi < 2; mi++) {
            ldsm4(ah[mi], sb + OFF_AHI + aOff[mi] + ks * 32);
            ldsm4(al[mi], sb + OFF_ALO + aOff[mi] + ks * 32);
        }
        #pragma unroll
        for (int nt = 0; nt < 2; nt++) {
            ldsm4(bh[nt], sb + OFF_BHI + bOff[nt] + ks * 32);
            ldsm4(bl[nt], sb + OFF_BLO + bOff[nt] + ks * 32);
        }
        #pragma unroll
        for (int mi = 0; mi < 2; mi++) {
            #pragma unroll
            for (int ni = 0; ni < 4; ni++) {
                int nt = ni >> 1, j = ni & 1;
                uint32_t bhf[2] = { bh[nt][j], bh[nt][j + 2] };
                uint32_t blf[2] = { bl[nt][j], bl[nt][j + 2] };
                mma_bf16(acc[mi][ni], ah[mi], bhf);
                mma_bf16(acc[mi][ni], ah[mi], blf);
                mma_bf16(acc[mi][ni], al[mi], bhf);
            }
        }
    }
}

// fp32 -> (hi, lo) bf16 split
__device__ __forceinline__ void split2(float v0, float v1, uint32_t& hw, uint32_t& lw) {
    __nv_bfloat162 h = __floats2bfloat162_rn(v0, v1);
    float r0 = v0 - __bfloat162float(h.x);
    float r1 = v1 - __bfloat162float(h.y);
    __nv_bfloat162 l = __floats2bfloat162_rn(r0, r1);
    hw = *reinterpret_cast<uint32_t*>(&h);
    lw = *reinterpret_cast<uint32_t*>(&l);
}

// ---------------- GEMM1: h = relu(gather(x) @ W1t + b1) -> hi/lo bf16 ------------
__global__ __launch_bounds__(512, 1) void gemm1_kernel(const float* __restrict__ b1) {
    extern __shared__ char smem[];
    const int e = blockIdx.z;
    const int cnt = g_count[e];
    const int m_base = blockIdx.y * 128;
    if (m_base >= cnt) return;
    const int off = g_off[e];
    const int n_base = blockIdx.x * 128;
    const int tid = threadIdx.x;
    const int w = tid >> 5, lane = tid & 31;
    const int wm = w & 3, wn = w >> 2;

    LoadCtx L;
    {
        int rowIdx = tid >> 2;
        int gm = m_base + rowIdx;
        int tok = g_list_tok[off + ((gm < cnt) ? gm : 0)];
        L.aHi = (const char*)(g_xhi + (size_t)tok * H_DIM);
        L.aLo = (const char*)(g_xlo + (size_t)tok * H_DIM);
        size_t rB = ((size_t)e * I_DIM + (n_base + rowIdx)) * H_DIM;
        L.bHi = (const char*)(g_w1t_hi + rB);
        L.bLo = (const char*)(g_w1t_lo + rB);
        L.gOff = (tid & 3) * 32;
        L.sRow = (uint32_t)rowIdx * ROWB + L.gOff;
        L.smem0 = smem_to_u32(smem);
    }

    uint32_t aOff[2], bOff[2];
    {
        int mat = lane >> 3, lr = lane & 7;
        uint32_t kb = (uint32_t)(lane >> 4) * 16;
        #pragma unroll
        for (int mi = 0; mi < 2; mi++)
            aOff[mi] = (uint32_t)(wm * 32 + mi * 16 + ((mat & 1) << 3) + lr) * ROWB + kb;
        #pragma unroll
        for (int nt = 0; nt < 2; nt++)
            bOff[nt] = (uint32_t)(wn * 32 + nt * 16 + ((mat & 1) << 3) + lr) * ROWB + kb;
    }

    float acc[2][4][4] = {};

    const int NC = H_DIM / KC;   // 8
    issue_stage(L, 0, 0);   CP_COMMIT();
    issue_stage(L, 1, KC);  CP_COMMIT();
    for (int c = 0; c < NC; c++) {
        if (c + 2 < NC) CP_WAIT1(); else CP_WAIT0();
        __syncthreads();
        if (c + 2 < NC) { issue_stage(L, (c + 2) % NSTAGE, (c + 2) * KC); CP_COMMIT(); }
        compute_stage(L.smem0 + (c % NSTAGE) * STG_BYTES, aOff, bOff, acc);
    }

    int qrow = lane >> 2, qcol = (lane & 3) * 2;
    #pragma unroll
    for (int mi = 0; mi < 2; mi++) {
        #pragma unroll
        for (int half = 0; half < 2; half++) {
            int row = wm * 32 + mi * 16 + qrow + half * 8;
            int gm = m_base + row;
            if (gm >= cnt) continue;
            size_t pair = (size_t)(off + gm);
            #pragma unroll
            for (int ni = 0; ni < 4; ni++) {
                int n = n_base + wn * 32 + ni * 8 + qcol;
                float v0 = fmaxf(acc[mi][ni][half * 2 + 0] + b1[e * I_DIM + n],     0.f);
                float v1 = fmaxf(acc[mi][ni][half * 2 + 1] + b1[e * I_DIM + n + 1], 0.f);
                uint32_t hw, lw;
                split2(v0, v1, hw, lw);
                *reinterpret_cast<uint32_t*>(g_hhi + pair * I_DIM + n) = hw;
                *reinterpret_cast<uint32_t*>(g_hlo + pair * I_DIM + n) = lw;
            }
        }
    }
}

// ---------------- GEMM2: out[tok] += wgt * (h @ W2t + b2) ------------------------
__global__ __launch_bounds__(512, 1) void gemm2_kernel(const float* __restrict__ b2,
                                                       float* __restrict__ out) {
    extern __shared__ char smem[];
    const int e = blockIdx.z;
    const int cnt = g_count[e];
    const int m_base = blockIdx.y * 128;
    if (m_base >= cnt) return;
    const int off = g_off[e];
    const int n_base = blockIdx.x * 128;
    const int tid = threadIdx.x;
    const int w = tid >> 5, lane = tid & 31;
    const int wm = w & 3, wn = w >> 2;

    LoadCtx L;
    {
        int rowIdx = tid >> 2;
        int gm = m_base + rowIdx;
        size_t pr = (size_t)(off + ((gm < cnt) ? gm : 0));
        L.aHi = (const char*)(g_hhi + pr * I_DIM);
        L.aLo = (const char*)(g_hlo + pr * I_DIM);
        size_t rB = ((size_t)e * H_DIM + (n_base + rowIdx)) * I_DIM;
        L.bHi = (const char*)(g_w2t_hi + rB);
        L.bLo = (const char*)(g_w2t_lo + rB);
        L.gOff = (tid & 3) * 32;
        L.sRow = (uint32_t)rowIdx * ROWB + L.gOff;
        L.smem0 = smem_to_u32(smem);
    }

    uint32_t aOff[2], bOff[2];
    {
        int mat = lane >> 3, lr = lane & 7;
        uint32_t kb = (uint32_t)(lane >> 4) * 16;
        #pragma unroll
        for (int mi = 0; mi < 2; mi++)
            aOff[mi] = (uint32_t)(wm * 32 + mi * 16 + ((mat & 1) << 3) + lr) * ROWB + kb;
        #pragma unroll
        for (int nt = 0; nt < 2; nt++)
            bOff[nt] = (uint32_t)(wn * 32 + nt * 16 + ((mat & 1) << 3) + lr) * ROWB + kb;
    }

    float acc[2][4][4] = {};

    const int NC = I_DIM / KC;   // 16
    issue_stage(L, 0, 0);   CP_COMMIT();
    issue_stage(L, 1, KC);  CP_COMMIT();
    for (int c = 0; c < NC; c++) {
        if (c + 2 < NC) CP_WAIT1(); else CP_WAIT0();
        __syncthreads();
        if (c + 2 < NC) { issue_stage(L, (c + 2) % NSTAGE, (c + 2) * KC); CP_COMMIT(); }
        compute_stage(L.smem0 + (c % NSTAGE) * STG_BYTES, aOff, bOff, acc);
    }

    int qrow = lane >> 2, qcol = (lane & 3) * 2;
    #pragma unroll
    for (int mi = 0; mi < 2; mi++) {
        #pragma unroll
        for (int half = 0; half < 2; half++) {
            int row = wm * 32 + mi * 16 + qrow + half * 8;
            int gm = m_base + row;
            if (gm >= cnt) continue;
            int tok = g_list_tok[off + gm];
            float wgt = g_list_w[off + gm];
            float* dst = out + (size_t)tok * H_DIM;
            #pragma unroll
            for (int ni = 0; ni < 4; ni++) {
                int n = n_base + wn * 32 + ni * 8 + qcol;
                atomicAdd(&dst[n],     wgt * (acc[mi][ni][half * 2 + 0] + b2[e * H_DIM + n]));
                atomicAdd(&dst[n + 1], wgt * (acc[mi][ni][half * 2 + 1] + b2[e * H_DIM + n + 1]));
            }
        }
    }
}

// ---------------- launch ----------------------------------------------------------
extern "C" void kernel_launch(void* const* d_in, const int* in_sizes, int n_in,
                              void* d_out, int out_size) {
    const float* x  = (const float*)d_in[0];
    const float* gw = (const float*)d_in[1];
    const float* w1 = (const float*)d_in[2];
    const float* b1 = (const float*)d_in[3];
    const float* w2 = (const float*)d_in[4];
    const float* b2 = (const float*)d_in[5];
    float* out = (float*)d_out;
    float* logits = out + (size_t)T_TOKENS * H_DIM;

    cudaFuncSetAttribute(gemm1_kernel, cudaFuncAttributeMaxDynamicSharedMemorySize, SMEM_BYTES);
    cudaFuncSetAttribute(gemm2_kernel, cudaFuncAttributeMaxDynamicSharedMemorySize, SMEM_BYTES);

    router_kernel<<<T_TOKENS / 8, 256>>>(x, gw, logits, (float4*)out);
    scan_scatter_kernel<<<1, 1024>>>();

    wconv1_kernel<<<dim3(I_DIM / 32, H_DIM / 32, E_NUM), dim3(32, 8)>>>(w1);
    wconv2_kernel<<<dim3(H_DIM / 32, I_DIM / 32, E_NUM), dim3(32, 8)>>>(w2);

    dim3 g1(I_DIM / 128, T_TOKENS / 128, E_NUM);
    gemm1_kernel<<<g1, 512, SMEM_BYTES>>>(b1);

    dim3 g2(H_DIM / 128, T_TOKENS / 128, E_NUM);
    gemm2_kernel<<<g2, 512, SMEM_BYTES>>>(b2, out);
}

// round 6
// speedup vs baseline: 2.9683x; 1.3123x over previous
#include <cuda_runtime.h>
#include <cuda_fp16.h>
#include <cstdint>
#include <math.h>

#define T_TOKENS 8192
#define H_DIM    512
#define I_DIM    1024
#define E_NUM    8
#define NP       (T_TOKENS * 2)
#define KC       64                      // K elems per stage (128B rows)

// ---------------- smem layout -------------------------------------------------
// per stage: 3 tiles (AHI, ALO, BHI), each 128 rows x 64 fp16,
// row stride 144B (128B data + 16B pad) -> conflict-free ldmatrix.
#define ROWB      144
#define TILE_SZ   (128 * ROWB)           // 18432 B
#define OFF_AHI   0
#define OFF_ALO   (1 * TILE_SZ)
#define OFF_BHI   (2 * TILE_SZ)
#define STG_BYTES (3 * TILE_SZ)          // 55296 B
#define NSTAGE    3
#define SMEM_BYTES (NSTAGE * STG_BYTES)  // 165888 B

// ---------------- PTX helpers ---------------------------------------------------
__device__ __forceinline__ uint32_t smem_to_u32(const void* p) {
    uint32_t a;
    asm("{ .reg .u64 t; cvta.to.shared.u64 t, %1; cvt.u32.u64 %0, t; }" : "=r"(a) : "l"(p));
    return a;
}
__device__ __forceinline__ void cp16(uint32_t s, const void* g) {
    asm volatile("cp.async.cg.shared.global [%0], [%1], 16;" :: "r"(s), "l"(g));
}
#define CP_COMMIT() asm volatile("cp.async.commit_group;" ::: "memory")
#define CP_WAIT1()  asm volatile("cp.async.wait_group 1;" ::: "memory")
#define CP_WAIT0()  asm volatile("cp.async.wait_group 0;" ::: "memory")

__device__ __forceinline__ void ldsm4(uint32_t* r, uint32_t a) {
    asm volatile("ldmatrix.sync.aligned.m8n8.x4.shared.b16 {%0,%1,%2,%3}, [%4];"
        : "=r"(r[0]), "=r"(r[1]), "=r"(r[2]), "=r"(r[3]) : "r"(a));
}
__device__ __forceinline__ void mma_f16(float* c, const uint32_t* a, const uint32_t* b) {
    asm volatile("mma.sync.aligned.m16n8k16.row.col.f32.f16.f16.f32 "
        "{%0,%1,%2,%3}, {%4,%5,%6,%7}, {%8,%9}, {%0,%1,%2,%3};"
        : "+f"(c[0]), "+f"(c[1]), "+f"(c[2]), "+f"(c[3])
        : "r"(a[0]), "r"(a[1]), "r"(a[2]), "r"(a[3]), "r"(b[0]), "r"(b[1]));
}

// ---------------- scratch (device globals) -------------------------------------
__device__ int   g_count[E_NUM];
__device__ int   g_off[E_NUM + 1];
__device__ int   g_tok_e[T_TOKENS * 2];
__device__ float g_tok_w[T_TOKENS * 2];
__device__ int   g_list_tok[NP];
__device__ float g_list_w[NP];

__device__ __half g_xhi[(size_t)T_TOKENS * H_DIM];
__device__ __half g_xlo[(size_t)T_TOKENS * H_DIM];
__device__ __half g_w1t[(size_t)E_NUM * I_DIM * H_DIM];   // [e][n=I][k=H], fp16
__device__ __half g_w2t[(size_t)E_NUM * H_DIM * I_DIM];   // [e][n=H][k=I], fp16
__device__ __half g_hhi[(size_t)NP * I_DIM];
__device__ __half g_hlo[(size_t)NP * I_DIM];

// ---------------- router (fused: zero out-head, logits, top-2, x split) ---------
__global__ void router_kernel(const float* __restrict__ x,
                              const float* __restrict__ gw,
                              float* __restrict__ logits_out,
                              float4* __restrict__ out4) {
    int tid = threadIdx.x;
    #pragma unroll
    for (int i = 0; i < 4; i++)
        out4[(size_t)blockIdx.x * 1024 + i * 256 + tid] = make_float4(0.f, 0.f, 0.f, 0.f);

    int warp = tid >> 5, lane = tid & 31;
    int t = blockIdx.x * 8 + warp;

    float xr[16];
    #pragma unroll
    for (int j = 0; j < 16; j++) xr[j] = x[(size_t)t * H_DIM + lane + 32 * j];

    // fused x split -> fp16 hi/lo (2-limb, residual ~2^-22)
    #pragma unroll
    for (int j = 0; j < 16; j++) {
        __half h = __float2half_rn(xr[j]);
        float r = xr[j] - __half2float(h);
        __half l = __float2half_rn(r);
        g_xhi[(size_t)t * H_DIM + lane + 32 * j] = h;
        g_xlo[(size_t)t * H_DIM + lane + 32 * j] = l;
    }

    float lg[E_NUM];
    #pragma unroll
    for (int e = 0; e < E_NUM; e++) {
        float s = 0.f;
        const float* g = gw + (size_t)e * H_DIM + lane;
        #pragma unroll
        for (int j = 0; j < 16; j++) s = fmaf(xr[j], g[32 * j], s);
        #pragma unroll
        for (int o = 16; o; o >>= 1) s += __shfl_xor_sync(0xffffffffu, s, o);
        lg[e] = s;
    }
    if (lane == 0) {
        float m = lg[0];
        #pragma unroll
        for (int e = 1; e < E_NUM; e++) m = fmaxf(m, lg[e]);
        float p[E_NUM], sum = 0.f;
        #pragma unroll
        for (int e = 0; e < E_NUM; e++) { p[e] = expf(lg[e] - m); sum += p[e]; }
        float inv = 1.f / sum;
        #pragma unroll
        for (int e = 0; e < E_NUM; e++) {
            p[e] *= inv;
            logits_out[(size_t)t * E_NUM + e] = lg[e];
        }
        int i0 = 0;
        #pragma unroll
        for (int e = 1; e < E_NUM; e++) if (p[e] > p[i0]) i0 = e;
        int i1 = (i0 == 0) ? 1 : 0;
        #pragma unroll
        for (int e = 0; e < E_NUM; e++) if (e != i1 && e != i0 && p[e] > p[i1]) i1 = e;
        float w0 = p[i0], w1 = p[i1];
        float s2 = w0 + w1 + 1e-20f;
        w0 = (w0 / s2) * 0.5f;
        w1 = (w1 / s2) * 0.5f;
        g_tok_e[t * 2 + 0] = i0;  g_tok_w[t * 2 + 0] = w0;
        g_tok_e[t * 2 + 1] = i1;  g_tok_w[t * 2 + 1] = w1;
    }
}

// ---------------- scan+scatter (single block) ------------------------------------
__global__ void scan_scatter_kernel() {
    __shared__ int s_cnt[E_NUM];
    __shared__ int s_cur[E_NUM];
    int tid = threadIdx.x;
    int lane = tid & 31;
    if (tid < E_NUM) s_cnt[tid] = 0;
    __syncthreads();

    int local[E_NUM] = {};
    for (int i = tid; i < NP; i += 1024) {
        int e = g_tok_e[i];
        #pragma unroll
        for (int q = 0; q < E_NUM; q++) local[q] += (e == q);
    }
    #pragma unroll
    for (int q = 0; q < E_NUM; q++) {
        int v = local[q];
        #pragma unroll
        for (int o = 16; o; o >>= 1) v += __shfl_down_sync(0xffffffffu, v, o);
        if (lane == 0 && v) atomicAdd(&s_cnt[q], v);
    }
    __syncthreads();
    if (tid == 0) {
        int o = 0;
        #pragma unroll
        for (int e = 0; e < E_NUM; e++) {
            g_off[e] = o; s_cur[e] = o; o += s_cnt[e];
        }
        g_off[E_NUM] = o;
    }
    __syncthreads();
    if (tid < E_NUM) g_count[tid] = s_cnt[tid];
    for (int i = tid; i < NP; i += 1024) {
        int e = g_tok_e[i];
        int pos = atomicAdd(&s_cur[e], 1);
        g_list_tok[pos] = i >> 1;
        g_list_w[pos]   = g_tok_w[i];
    }
}

// ---------------- weight convert+transpose -> single fp16 ------------------------
__device__ __forceinline__ void wconv_body(const float* __restrict__ W,
                                           __half* __restrict__ wh,
                                           int K, int N) {
    __shared__ float s[32][33];
    int e = blockIdx.z;
    int k0 = blockIdx.y * 32, n0 = blockIdx.x * 32;
    const float* src = W + (size_t)e * K * N;
    int tx = threadIdx.x, ty = threadIdx.y;
    #pragma unroll
    for (int i = 0; i < 4; i++)
        s[ty + 8 * i][tx] = src[(size_t)(k0 + ty + 8 * i) * N + n0 + tx];
    __syncthreads();
    size_t ob = (size_t)e * N * K;
    #pragma unroll
    for (int i = 0; i < 4; i++) {
        int n = n0 + ty + 8 * i;
        wh[ob + (size_t)n * K + k0 + tx] = __float2half_rn(s[tx][ty + 8 * i]);
    }
}
__global__ void wconv1_kernel(const float* __restrict__ W) { wconv_body(W, g_w1t, H_DIM, I_DIM); }
__global__ void wconv2_kernel(const float* __restrict__ W) { wconv_body(W, g_w2t, I_DIM, H_DIM); }

// ---------------- GEMM core ------------------------------------------------------
struct LoadCtx {
    const char *aHi, *aLo, *bHi;
    uint32_t sRow, gOff, smem0;
};

__device__ __forceinline__ void issue_stage(const LoadCtx& L, int s, int k0elem) {
    uint32_t sb = L.smem0 + s * STG_BYTES + L.sRow;
    size_t gk = (size_t)k0elem * 2 + L.gOff;
    cp16(sb + OFF_AHI,      L.aHi + gk);
    cp16(sb + OFF_AHI + 16, L.aHi + gk + 16);
    cp16(sb + OFF_ALO,      L.aLo + gk);
    cp16(sb + OFF_ALO + 16, L.aLo + gk + 16);
    cp16(sb + OFF_BHI,      L.bHi + gk);
    cp16(sb + OFF_BHI + 16, L.bHi + gk + 16);
}

__device__ __forceinline__ void compute_stage(uint32_t sb,
        const uint32_t* aOff, const uint32_t* bOff, float acc[2][4][4]) {
    #pragma unroll
    for (int ks = 0; ks < 4; ks++) {
        uint32_t ah[2][4], al[2][4], bh[2][4];
        #pragma unroll
        for (int mi = 0; mi < 2; mi++) {
            ldsm4(ah[mi], sb + OFF_AHI + aOff[mi] + ks * 32);
            ldsm4(al[mi], sb + OFF_ALO + aOff[mi] + ks * 32);
        }
        #pragma unroll
        for (int nt = 0; nt < 2; nt++)
            ldsm4(bh[nt], sb + OFF_BHI + bOff[nt] + ks * 32);
        #pragma unroll
        for (int mi = 0; mi < 2; mi++) {
            #pragma unroll
            for (int ni = 0; ni < 4; ni++) {
                int nt = ni >> 1, j = ni & 1;
                uint32_t bhf[2] = { bh[nt][j], bh[nt][j + 2] };
                mma_f16(acc[mi][ni], ah[mi], bhf);
                mma_f16(acc[mi][ni], al[mi], bhf);
            }
        }
    }
}

// fp32 -> (hi, lo) fp16 split (packed pair)
__device__ __forceinline__ void split2h(float v0, float v1, uint32_t& hw, uint32_t& lw) {
    __half2 h = __floats2half2_rn(v0, v1);
    float r0 = v0 - __half2float(__low2half(h));
    float r1 = v1 - __half2float(__high2half(h));
    __half2 l = __floats2half2_rn(r0, r1);
    hw = *reinterpret_cast<uint32_t*>(&h);
    lw = *reinterpret_cast<uint32_t*>(&l);
}

// ---------------- GEMM1: h = relu(gather(x) @ W1t + b1) -> hi/lo fp16 ------------
__global__ __launch_bounds__(512, 1) void gemm1_kernel(const float* __restrict__ b1) {
    extern __shared__ char smem[];
    const int e = blockIdx.z;
    const int cnt = g_count[e];
    const int m_base = blockIdx.y * 128;
    if (m_base >= cnt) return;
    const int off = g_off[e];
    const int n_base = blockIdx.x * 128;
    const int tid = threadIdx.x;
    const int w = tid >> 5, lane = tid & 31;
    const int wm = w & 3, wn = w >> 2;

    LoadCtx L;
    {
        int rowIdx = tid >> 2;
        int gm = m_base + rowIdx;
        int tok = g_list_tok[off + ((gm < cnt) ? gm : 0)];
        L.aHi = (const char*)(g_xhi + (size_t)tok * H_DIM);
        L.aLo = (const char*)(g_xlo + (size_t)tok * H_DIM);
        size_t rB = ((size_t)e * I_DIM + (n_base + rowIdx)) * H_DIM;
        L.bHi = (const char*)(g_w1t + rB);
        L.gOff = (tid & 3) * 32;
        L.sRow = (uint32_t)rowIdx * ROWB + L.gOff;
        L.smem0 = smem_to_u32(smem);
    }

    uint32_t aOff[2], bOff[2];
    {
        int mat = lane >> 3, lr = lane & 7;
        uint32_t kb = (uint32_t)(lane >> 4) * 16;
        #pragma unroll
        for (int mi = 0; mi < 2; mi++)
            aOff[mi] = (uint32_t)(wm * 32 + mi * 16 + ((mat & 1) << 3) + lr) * ROWB + kb;
        #pragma unroll
        for (int nt = 0; nt < 2; nt++)
            bOff[nt] = (uint32_t)(wn * 32 + nt * 16 + ((mat & 1) << 3) + lr) * ROWB + kb;
    }

    float acc[2][4][4] = {};

    const int NC = H_DIM / KC;   // 8
    issue_stage(L, 0, 0);   CP_COMMIT();
    issue_stage(L, 1, KC);  CP_COMMIT();
    for (int c = 0; c < NC; c++) {
        if (c + 2 < NC) CP_WAIT1(); else CP_WAIT0();
        __syncthreads();
        if (c + 2 < NC) { issue_stage(L, (c + 2) % NSTAGE, (c + 2) * KC); CP_COMMIT(); }
        compute_stage(L.smem0 + (c % NSTAGE) * STG_BYTES, aOff, bOff, acc);
    }

    int qrow = lane >> 2, qcol = (lane & 3) * 2;
    #pragma unroll
    for (int mi = 0; mi < 2; mi++) {
        #pragma unroll
        for (int half = 0; half < 2; half++) {
            int row = wm * 32 + mi * 16 + qrow + half * 8;
            int gm = m_base + row;
            if (gm >= cnt) continue;
            size_t pair = (size_t)(off + gm);
            #pragma unroll
            for (int ni = 0; ni < 4; ni++) {
                int n = n_base + wn * 32 + ni * 8 + qcol;
                float v0 = fmaxf(acc[mi][ni][half * 2 + 0] + b1[e * I_DIM + n],     0.f);
                float v1 = fmaxf(acc[mi][ni][half * 2 + 1] + b1[e * I_DIM + n + 1], 0.f);
                uint32_t hw, lw;
                split2h(v0, v1, hw, lw);
                *reinterpret_cast<uint32_t*>(g_hhi + pair * I_DIM + n) = hw;
                *reinterpret_cast<uint32_t*>(g_hlo + pair * I_DIM + n) = lw;
            }
        }
    }
}

// ---------------- GEMM2: out[tok] += wgt * (h @ W2t + b2) ------------------------
__global__ __launch_bounds__(512, 1) void gemm2_kernel(const float* __restrict__ b2,
                                                       float* __restrict__ out) {
    extern __shared__ char smem[];
    const int e = blockIdx.z;
    const int cnt = g_count[e];
    const int m_base = blockIdx.y * 128;
    if (m_base >= cnt) return;
    const int off = g_off[e];
    const int n_base = blockIdx.x * 128;
    const int tid = threadIdx.x;
    const int w = tid >> 5, lane = tid & 31;
    const int wm = w & 3, wn = w >> 2;

    LoadCtx L;
    {
        int rowIdx = tid >> 2;
        int gm = m_base + rowIdx;
        size_t pr = (size_t)(off + ((gm < cnt) ? gm : 0));
        L.aHi = (const char*)(g_hhi + pr * I_DIM);
        L.aLo = (const char*)(g_hlo + pr * I_DIM);
        size_t rB = ((size_t)e * H_DIM + (n_base + rowIdx)) * I_DIM;
        L.bHi = (const char*)(g_w2t + rB);
        L.gOff = (tid & 3) * 32;
        L.sRow = (uint32_t)rowIdx * ROWB + L.gOff;
        L.smem0 = smem_to_u32(smem);
    }

    uint32_t aOff[2], bOff[2];
    {
        int mat = lane >> 3, lr = lane & 7;
        uint32_t kb = (uint32_t)(lane >> 4) * 16;
        #pragma unroll
        for (int mi = 0; mi < 2; mi++)
            aOff[mi] = (uint32_t)(wm * 32 + mi * 16 + ((mat & 1) << 3) + lr) * ROWB + kb;
        #pragma unroll
        for (int nt = 0; nt < 2; nt++)
            bOff[nt] = (uint32_t)(wn * 32 + nt * 16 + ((mat & 1) << 3) + lr) * ROWB + kb;
    }

    float acc[2][4][4] = {};

    const int NC = I_DIM / KC;   // 16
    issue_stage(L, 0, 0);   CP_COMMIT();
    issue_stage(L, 1, KC);  CP_COMMIT();
    for (int c = 0; c < NC; c++) {
        if (c + 2 < NC) CP_WAIT1(); else CP_WAIT0();
        __syncthreads();
        if (c + 2 < NC) { issue_stage(L, (c + 2) % NSTAGE, (c + 2) * KC); CP_COMMIT(); }
        compute_stage(L.smem0 + (c % NSTAGE) * STG_BYTES, aOff, bOff, acc);
    }

    int qrow = lane >> 2, qcol = (lane & 3) * 2;
    #pragma unroll
    for (int mi = 0; mi < 2; mi++) {
        #pragma unroll
        for (int half = 0; half < 2; half++) {
            int row = wm * 32 + mi * 16 + qrow + half * 8;
            int gm = m_base + row;
            if (gm >= cnt) continue;
            int tok = g_list_tok[off + gm];
            float wgt = g_list_w[off + gm];
            float* dst = out + (size_t)tok * H_DIM;
            #pragma unroll
            for (int ni = 0; ni < 4; ni++) {
                int n = n_base + wn * 32 + ni * 8 + qcol;
                atomicAdd(&dst[n],     wgt * (acc[mi][ni][half * 2 + 0] + b2[e * H_DIM + n]));
                atomicAdd(&dst[n + 1], wgt * (acc[mi][ni][half * 2 + 1] + b2[e * H_DIM + n + 1]));
            }
        }
    }
}

// ---------------- launch ----------------------------------------------------------
extern "C" void kernel_launch(void* const* d_in, const int* in_sizes, int n_in,
                              void* d_out, int out_size) {
    const float* x  = (const float*)d_in[0];
    const float* gw = (const float*)d_in[1];
    const float* w1 = (const float*)d_in[2];
    const float* b1 = (const float*)d_in[3];
    const float* w2 = (const float*)d_in[4];
    const float* b2 = (const float*)d_in[5];
    float* out = (float*)d_out;
    float* logits = out + (size_t)T_TOKENS * H_DIM;

    cudaFuncSetAttribute(gemm1_kernel, cudaFuncAttributeMaxDynamicSharedMemorySize, SMEM_BYTES);
    cudaFuncSetAttribute(gemm2_kernel, cudaFuncAttributeMaxDynamicSharedMemorySize, SMEM_BYTES);

    router_kernel<<<T_TOKENS / 8, 256>>>(x, gw, logits, (float4*)out);
    scan_scatter_kernel<<<1, 1024>>>();

    wconv1_kernel<<<dim3(I_DIM / 32, H_DIM / 32, E_NUM), dim3(32, 8)>>>(w1);
    wconv2_kernel<<<dim3(H_DIM / 32, I_DIM / 32, E_NUM), dim3(32, 8)>>>(w2);

    dim3 g1(I_DIM / 128, T_TOKENS / 128, E_NUM);
    gemm1_kernel<<<g1, 512, SMEM_BYTES>>>(b1);

    dim3 g2(H_DIM / 128, T_TOKENS / 128, E_NUM);
    gemm2_kernel<<<g2, 512, SMEM_BYTES>>>(b2, out);
}

// round 7
// speedup vs baseline: 4.6520x; 1.5672x over previous
#include <cuda_runtime.h>
#include <cuda_fp16.h>
#include <cstdint>
#include <math.h>

#define T_TOKENS 8192
#define H_DIM    512
#define I_DIM    1024
#define E_NUM    8
#define NP       (T_TOKENS * 2)
#define KC       64                      // K elems per stage (128B rows)

// ---------------- smem layout -------------------------------------------------
// per stage: 2 tiles (A, B), each 128 rows x 64 fp16, row stride 144B.
#define ROWB      144
#define TILE_SZ   (128 * ROWB)           // 18432 B
#define OFF_A     0
#define OFF_B     TILE_SZ
#define STG_BYTES (2 * TILE_SZ)          // 36864 B
#define NSTAGE    3
#define SMEM_BYTES (NSTAGE * STG_BYTES)  // 110592 B

// ---------------- PTX helpers ---------------------------------------------------
__device__ __forceinline__ uint32_t smem_to_u32(const void* p) {
    uint32_t a;
    asm("{ .reg .u64 t; cvta.to.shared.u64 t, %1; cvt.u32.u64 %0, t; }" : "=r"(a) : "l"(p));
    return a;
}
__device__ __forceinline__ void cp16(uint32_t s, const void* g) {
    asm volatile("cp.async.cg.shared.global [%0], [%1], 16;" :: "r"(s), "l"(g));
}
#define CP_COMMIT() asm volatile("cp.async.commit_group;" ::: "memory")
#define CP_WAIT1()  asm volatile("cp.async.wait_group 1;" ::: "memory")
#define CP_WAIT0()  asm volatile("cp.async.wait_group 0;" ::: "memory")

__device__ __forceinline__ void ldsm4(uint32_t* r, uint32_t a) {
    asm volatile("ldmatrix.sync.aligned.m8n8.x4.shared.b16 {%0,%1,%2,%3}, [%4];"
        : "=r"(r[0]), "=r"(r[1]), "=r"(r[2]), "=r"(r[3]) : "r"(a));
}
__device__ __forceinline__ void mma_f16(float* c, const uint32_t* a, const uint32_t* b) {
    asm volatile("mma.sync.aligned.m16n8k16.row.col.f32.f16.f16.f32 "
        "{%0,%1,%2,%3}, {%4,%5,%6,%7}, {%8,%9}, {%0,%1,%2,%3};"
        : "+f"(c[0]), "+f"(c[1]), "+f"(c[2]), "+f"(c[3])
        : "r"(a[0]), "r"(a[1]), "r"(a[2]), "r"(a[3]), "r"(b[0]), "r"(b[1]));
}

// ---------------- scratch (device globals) -------------------------------------
__device__ int   g_count[E_NUM];
__device__ int   g_off[E_NUM + 1];
__device__ int   g_tok_e[T_TOKENS * 2];
__device__ float g_tok_w[T_TOKENS * 2];
__device__ int   g_list_tok[NP];
__device__ float g_list_w[NP];

__device__ __half g_xh[(size_t)T_TOKENS * H_DIM];
__device__ __half g_w1t[(size_t)E_NUM * I_DIM * H_DIM];   // [e][n=I][k=H]
__device__ __half g_w2t[(size_t)E_NUM * H_DIM * I_DIM];   // [e][n=H][k=I]
__device__ __half g_h[(size_t)NP * I_DIM];

// ---------------- router (fused: zero out-head, logits, top-2, x->fp16) ---------
__global__ void router_kernel(const float* __restrict__ x,
                              const float* __restrict__ gw,
                              float* __restrict__ logits_out,
                              float4* __restrict__ out4) {
    int tid = threadIdx.x;
    #pragma unroll
    for (int i = 0; i < 4; i++)
        out4[(size_t)blockIdx.x * 1024 + i * 256 + tid] = make_float4(0.f, 0.f, 0.f, 0.f);

    int warp = tid >> 5, lane = tid & 31;
    int t = blockIdx.x * 8 + warp;

    float xr[16];
    #pragma unroll
    for (int j = 0; j < 16; j++) xr[j] = x[(size_t)t * H_DIM + lane + 32 * j];

    #pragma unroll
    for (int j = 0; j < 16; j++)
        g_xh[(size_t)t * H_DIM + lane + 32 * j] = __float2half_rn(xr[j]);

    float lg[E_NUM];
    #pragma unroll
    for (int e = 0; e < E_NUM; e++) {
        float s = 0.f;
        const float* g = gw + (size_t)e * H_DIM + lane;
        #pragma unroll
        for (int j = 0; j < 16; j++) s = fmaf(xr[j], g[32 * j], s);
        #pragma unroll
        for (int o = 16; o; o >>= 1) s += __shfl_xor_sync(0xffffffffu, s, o);
        lg[e] = s;
    }
    if (lane == 0) {
        float m = lg[0];
        #pragma unroll
        for (int e = 1; e < E_NUM; e++) m = fmaxf(m, lg[e]);
        float p[E_NUM], sum = 0.f;
        #pragma unroll
        for (int e = 0; e < E_NUM; e++) { p[e] = expf(lg[e] - m); sum += p[e]; }
        float inv = 1.f / sum;
        #pragma unroll
        for (int e = 0; e < E_NUM; e++) {
            p[e] *= inv;
            logits_out[(size_t)t * E_NUM + e] = lg[e];
        }
        int i0 = 0;
        #pragma unroll
        for (int e = 1; e < E_NUM; e++) if (p[e] > p[i0]) i0 = e;
        int i1 = (i0 == 0) ? 1 : 0;
        #pragma unroll
        for (int e = 0; e < E_NUM; e++) if (e != i1 && e != i0 && p[e] > p[i1]) i1 = e;
        float w0 = p[i0], w1 = p[i1];
        float s2 = w0 + w1 + 1e-20f;
        w0 = (w0 / s2) * 0.5f;
        w1 = (w1 / s2) * 0.5f;
        g_tok_e[t * 2 + 0] = i0;  g_tok_w[t * 2 + 0] = w0;
        g_tok_e[t * 2 + 1] = i1;  g_tok_w[t * 2 + 1] = w1;
    }
}

// ---------------- scan+scatter (single block) ------------------------------------
__global__ void scan_scatter_kernel() {
    __shared__ int s_cnt[E_NUM];
    __shared__ int s_cur[E_NUM];
    int tid = threadIdx.x;
    int lane = tid & 31;
    if (tid < E_NUM) s_cnt[tid] = 0;
    __syncthreads();

    int local[E_NUM] = {};
    for (int i = tid; i < NP; i += 1024) {
        int e = g_tok_e[i];
        #pragma unroll
        for (int q = 0; q < E_NUM; q++) local[q] += (e == q);
    }
    #pragma unroll
    for (int q = 0; q < E_NUM; q++) {
        int v = local[q];
        #pragma unroll
        for (int o = 16; o; o >>= 1) v += __shfl_down_sync(0xffffffffu, v, o);
        if (lane == 0 && v) atomicAdd(&s_cnt[q], v);
    }
    __syncthreads();
    if (tid == 0) {
        int o = 0;
        #pragma unroll
        for (int e = 0; e < E_NUM; e++) {
            g_off[e] = o; s_cur[e] = o; o += s_cnt[e];
        }
        g_off[E_NUM] = o;
    }
    __syncthreads();
    if (tid < E_NUM) g_count[tid] = s_cnt[tid];
    for (int i = tid; i < NP; i += 1024) {
        int e = g_tok_e[i];
        int pos = atomicAdd(&s_cur[e], 1);
        g_list_tok[pos] = i >> 1;
        g_list_w[pos]   = g_tok_w[i];
    }
}

// ---------------- weight convert+transpose -> fp16 -------------------------------
__device__ __forceinline__ void wconv_body(const float* __restrict__ W,
                                           __half* __restrict__ wh,
                                           int K, int N) {
    __shared__ float s[32][33];
    int e = blockIdx.z;
    int k0 = blockIdx.y * 32, n0 = blockIdx.x * 32;
    const float* src = W + (size_t)e * K * N;
    int tx = threadIdx.x, ty = threadIdx.y;
    #pragma unroll
    for (int i = 0; i < 4; i++)
        s[ty + 8 * i][tx] = src[(size_t)(k0 + ty + 8 * i) * N + n0 + tx];
    __syncthreads();
    size_t ob = (size_t)e * N * K;
    #pragma unroll
    for (int i = 0; i < 4; i++) {
        int n = n0 + ty + 8 * i;
        wh[ob + (size_t)n * K + k0 + tx] = __float2half_rn(s[tx][ty + 8 * i]);
    }
}
__global__ void wconv1_kernel(const float* __restrict__ W) { wconv_body(W, g_w1t, H_DIM, I_DIM); }
__global__ void wconv2_kernel(const float* __restrict__ W) { wconv_body(W, g_w2t, I_DIM, H_DIM); }

// ---------------- GEMM core ------------------------------------------------------
struct LoadCtx {
    const char *aP, *bP;
    uint32_t sRow, gOff, smem0;
};

__device__ __forceinline__ void issue_stage(const LoadCtx& L, int s, int k0elem) {
    uint32_t sb = L.smem0 + s * STG_BYTES + L.sRow;
    size_t gk = (size_t)k0elem * 2 + L.gOff;
    cp16(sb + OFF_A,      L.aP + gk);
    cp16(sb + OFF_A + 16, L.aP + gk + 16);
    cp16(sb + OFF_B,      L.bP + gk);
    cp16(sb + OFF_B + 16, L.bP + gk + 16);
}

__device__ __forceinline__ void compute_stage(uint32_t sb,
        const uint32_t* aOff, const uint32_t* bOff, float acc[2][4][4]) {
    #pragma unroll
    for (int ks = 0; ks < 4; ks++) {
        uint32_t a[2][4], b[2][4];
        #pragma unroll
        for (int mi = 0; mi < 2; mi++)
            ldsm4(a[mi], sb + OFF_A + aOff[mi] + ks * 32);
        #pragma unroll
        for (int nt = 0; nt < 2; nt++)
            ldsm4(b[nt], sb + OFF_B + bOff[nt] + ks * 32);
        #pragma unroll
        for (int mi = 0; mi < 2; mi++) {
            #pragma unroll
            for (int ni = 0; ni < 4; ni++) {
                int nt = ni >> 1, j = ni & 1;
                uint32_t bf[2] = { b[nt][j], b[nt][j + 2] };
                mma_f16(acc[mi][ni], a[mi], bf);
            }
        }
    }
}

// ---------------- GEMM1: h = relu(gather(x) @ W1t + b1) -> fp16 ------------------
__global__ __launch_bounds__(512, 1) void gemm1_kernel(const float* __restrict__ b1) {
    extern __shared__ char smem[];
    const int e = blockIdx.z;
    const int cnt = g_count[e];
    const int m_base = blockIdx.y * 128;
    if (m_base >= cnt) return;
    const int off = g_off[e];
    const int n_base = blockIdx.x * 128;
    const int tid = threadIdx.x;
    const int w = tid >> 5, lane = tid & 31;
    const int wm = w & 3, wn = w >> 2;

    LoadCtx L;
    {
        int rowIdx = tid >> 2;
        int gm = m_base + rowIdx;
        int tok = g_list_tok[off + ((gm < cnt) ? gm : 0)];
        L.aP = (const char*)(g_xh + (size_t)tok * H_DIM);
        size_t rB = ((size_t)e * I_DIM + (n_base + rowIdx)) * H_DIM;
        L.bP = (const char*)(g_w1t + rB);
        L.gOff = (tid & 3) * 32;
        L.sRow = (uint32_t)rowIdx * ROWB + L.gOff;
        L.smem0 = smem_to_u32(smem);
    }

    uint32_t aOff[2], bOff[2];
    {
        int mat = lane >> 3, lr = lane & 7;
        uint32_t kb = (uint32_t)(lane >> 4) * 16;
        #pragma unroll
        for (int mi = 0; mi < 2; mi++)
            aOff[mi] = (uint32_t)(wm * 32 + mi * 16 + ((mat & 1) << 3) + lr) * ROWB + kb;
        #pragma unroll
        for (int nt = 0; nt < 2; nt++)
            bOff[nt] = (uint32_t)(wn * 32 + nt * 16 + ((mat & 1) << 3) + lr) * ROWB + kb;
    }

    float acc[2][4][4] = {};

    const int NC = H_DIM / KC;   // 8
    issue_stage(L, 0, 0);   CP_COMMIT();
    issue_stage(L, 1, KC);  CP_COMMIT();
    for (int c = 0; c < NC; c++) {
        if (c + 2 < NC) CP_WAIT1(); else CP_WAIT0();
        __syncthreads();
        if (c + 2 < NC) { issue_stage(L, (c + 2) % NSTAGE, (c + 2) * KC); CP_COMMIT(); }
        compute_stage(L.smem0 + (c % NSTAGE) * STG_BYTES, aOff, bOff, acc);
    }

    int qrow = lane >> 2, qcol = (lane & 3) * 2;
    #pragma unroll
    for (int mi = 0; mi < 2; mi++) {
        #pragma unroll
        for (int half = 0; half < 2; half++) {
            int row = wm * 32 + mi * 16 + qrow + half * 8;
            int gm = m_base + row;
            if (gm >= cnt) continue;
            size_t pair = (size_t)(off + gm);
            #pragma unroll
            for (int ni = 0; ni < 4; ni++) {
                int n = n_base + wn * 32 + ni * 8 + qcol;
                float v0 = fmaxf(acc[mi][ni][half * 2 + 0] + b1[e * I_DIM + n],     0.f);
                float v1 = fmaxf(acc[mi][ni][half * 2 + 1] + b1[e * I_DIM + n + 1], 0.f);
                __half2 hp = __floats2half2_rn(v0, v1);
                *reinterpret_cast<__half2*>(g_h + pair * I_DIM + n) = hp;
            }
        }
    }
}

// ---------------- GEMM2: out[tok] += wgt * (h @ W2t + b2) ------------------------
__global__ __launch_bounds__(512, 1) void gemm2_kernel(const float* __restrict__ b2,
                                                       float* __restrict__ out) {
    extern __shared__ char smem[];
    const int e = blockIdx.z;
    const int cnt = g_count[e];
    const int m_base = blockIdx.y * 128;
    if (m_base >= cnt) return;
    const int off = g_off[e];
    const int n_base = blockIdx.x * 128;
    const int tid = threadIdx.x;
    const int w = tid >> 5, lane = tid & 31;
    const int wm = w & 3, wn = w >> 2;

    LoadCtx L;
    {
        int rowIdx = tid >> 2;
        int gm = m_base + rowIdx;
        size_t pr = (size_t)(off + ((gm < cnt) ? gm : 0));
        L.aP = (const char*)(g_h + pr * I_DIM);
        size_t rB = ((size_t)e * H_DIM + (n_base + rowIdx)) * I_DIM;
        L.bP = (const char*)(g_w2t + rB);
        L.gOff = (tid & 3) * 32;
        L.sRow = (uint32_t)rowIdx * ROWB + L.gOff;
        L.smem0 = smem_to_u32(smem);
    }

    uint32_t aOff[2], bOff[2];
    {
        int mat = lane >> 3, lr = lane & 7;
        uint32_t kb = (uint32_t)(lane >> 4) * 16;
        #pragma unroll
        for (int mi = 0; mi < 2; mi++)
            aOff[mi] = (uint32_t)(wm * 32 + mi * 16 + ((mat & 1) << 3) + lr) * ROWB + kb;
        #pragma unroll
        for (int nt = 0; nt < 2; nt++)
            bOff[nt] = (uint32_t)(wn * 32 + nt * 16 + ((mat & 1) << 3) + lr) * ROWB + kb;
    }

    float acc[2][4][4] = {};

    const int NC = I_DIM / KC;   // 16
    issue_stage(L, 0, 0);   CP_COMMIT();
    issue_stage(L, 1, KC);  CP_COMMIT();
    for (int c = 0; c < NC; c++) {
        if (c + 2 < NC) CP_WAIT1(); else CP_WAIT0();
        __syncthreads();
        if (c + 2 < NC) { issue_stage(L, (c + 2) % NSTAGE, (c + 2) * KC); CP_COMMIT(); }
        compute_stage(L.smem0 + (c % NSTAGE) * STG_BYTES, aOff, bOff, acc);
    }

    int qrow = lane >> 2, qcol = (lane & 3) * 2;
    #pragma unroll
    for (int mi = 0; mi < 2; mi++) {
        #pragma unroll
        for (int half = 0; half < 2; half++) {
            int row = wm * 32 + mi * 16 + qrow + half * 8;
            int gm = m_base + row;
            if (gm >= cnt) continue;
            int tok = g_list_tok[off + gm];
            float wgt = g_list_w[off + gm];
            float* dst = out + (size_t)tok * H_DIM;
            #pragma unroll
            for (int ni = 0; ni < 4; ni++) {
                int n = n_base + wn * 32 + ni * 8 + qcol;
                atomicAdd(&dst[n],     wgt * (acc[mi][ni][half * 2 + 0] + b2[e * H_DIM + n]));
                atomicAdd(&dst[n + 1], wgt * (acc[mi][ni][half * 2 + 1] + b2[e * H_DIM + n + 1]));
            }
        }
    }
}

// ---------------- launch ----------------------------------------------------------
extern "C" void kernel_launch(void* const* d_in, const int* in_sizes, int n_in,
                              void* d_out, int out_size) {
    const float* x  = (const float*)d_in[0];
    const float* gw = (const float*)d_in[1];
    const float* w1 = (const float*)d_in[2];
    const float* b1 = (const float*)d_in[3];
    const float* w2 = (const float*)d_in[4];
    const float* b2 = (const float*)d_in[5];
    float* out = (float*)d_out;
    float* logits = out + (size_t)T_TOKENS * H_DIM;

    cudaFuncSetAttribute(gemm1_kernel, cudaFuncAttributeMaxDynamicSharedMemorySize, SMEM_BYTES);
    cudaFuncSetAttribute(gemm2_kernel, cudaFuncAttributeMaxDynamicSharedMemorySize, SMEM_BYTES);

    router_kernel<<<T_TOKENS / 8, 256>>>(x, gw, logits, (float4*)out);
    scan_scatter_kernel<<<1, 1024>>>();

    wconv1_kernel<<<dim3(I_DIM / 32, H_DIM / 32, E_NUM), dim3(32, 8)>>>(w1);
    wconv2_kernel<<<dim3(H_DIM / 32, I_DIM / 32, E_NUM), dim3(32, 8)>>>(w2);

    dim3 g1(I_DIM / 128, T_TOKENS / 128, E_NUM);
    gemm1_kernel<<<g1, 512, SMEM_BYTES>>>(b1);

    dim3 g2(H_DIM / 128, T_TOKENS / 128, E_NUM);
    gemm2_kernel<<<g2, 512, SMEM_BYTES>>>(b2, out);
}